// round 2
// baseline (speedup 1.0000x reference)
#include <cuda_runtime.h>

#define BATCH 2
#define SEQ   2048
#define CH    1024
#define NH    16
#define HD    64
#define MROWS (BATCH*SEQ)   /* 4096 */

// Scratch (allocation-free rule: __device__ globals)
__device__ float g_qkv[MROWS * 3 * CH];   // [4096, 3072]  ~50 MB
__device__ float g_y  [MROWS * CH];       // [4096, 1024]  ~17 MB

// ---------------------------------------------------------------------------
// SGEMM: C = A(MxK) @ B(KxN) (+bias), all row-major.
// Requires M%128==0, N%64==0, K%16==0 (true for all our shapes).
// BM=128, BN=64, BK=16, 256 threads, 8x4 microtile per thread.
// Fragment loads are LDS.128: A broadcast (2x float4), B conflict-free
// (16 consecutive float4 per half-warp phase covers banks 0..31 once).
// ---------------------------------------------------------------------------
template<bool HAS_BIAS>
__global__ __launch_bounds__(256)
void sgemm_kernel(const float* __restrict__ A, const float* __restrict__ B,
                  const float* __restrict__ bias, float* __restrict__ Cmat,
                  int Mx, int Nx, int Kx)
{
    constexpr int BM = 128, BN = 64, BK = 16;
    __shared__ float As[BK][BM + 4];   // transposed A tile: As[k][m], stride 132
    __shared__ float Bs[BK][BN + 4];   // Bs[k][n], stride 68

    const int tid = threadIdx.x;
    const int tx = tid & 15;           // 0..15 -> output col group (4 contiguous)
    const int ty = tid >> 4;           // 0..15 -> output row group (8 rows)
    const int bm = blockIdx.y * BM;
    const int bn = blockIdx.x * BN;

    float acc[8][4] = {};

    for (int k0 = 0; k0 < Kx; k0 += BK) {
        // Load A tile 128x16 = 512 float4s (2 per thread), store transposed
        #pragma unroll
        for (int t = 0; t < 2; t++) {
            int f   = tid + t * 256;       // 0..511
            int row = f >> 2;
            int c4  = (f & 3) * 4;
            float4 v = *(const float4*)&A[(size_t)(bm + row) * Kx + k0 + c4];
            As[c4 + 0][row] = v.x;
            As[c4 + 1][row] = v.y;
            As[c4 + 2][row] = v.z;
            As[c4 + 3][row] = v.w;
        }
        // Load B tile 16x64 = 256 float4s (1 per thread)
        {
            int row = tid >> 4;
            int c4  = (tid & 15) * 4;
            *(float4*)&Bs[row][c4] =
                *(const float4*)&B[(size_t)(k0 + row) * Nx + bn + c4];
        }
        __syncthreads();

        #pragma unroll
        for (int k = 0; k < BK; k++) {
            float4 a0 = *(const float4*)&As[k][ty * 8 + 0];   // broadcast
            float4 a1 = *(const float4*)&As[k][ty * 8 + 4];   // broadcast
            float4 b0 = *(const float4*)&Bs[k][tx * 4];       // conflict-free
            float ra[8] = {a0.x, a0.y, a0.z, a0.w, a1.x, a1.y, a1.z, a1.w};
            float rb[4] = {b0.x, b0.y, b0.z, b0.w};
            #pragma unroll
            for (int i = 0; i < 8; i++)
                #pragma unroll
                for (int j = 0; j < 4; j++)
                    acc[i][j] += ra[i] * rb[j];
        }
        __syncthreads();
    }

    #pragma unroll
    for (int i = 0; i < 8; i++) {
        int r = bm + ty * 8 + i;
        float4 v = make_float4(acc[i][0], acc[i][1], acc[i][2], acc[i][3]);
        if (HAS_BIAS) {
            float4 bb = *(const float4*)&bias[bn + tx * 4];
            v.x += bb.x; v.y += bb.y; v.z += bb.z; v.w += bb.w;
        }
        *(float4*)&Cmat[(size_t)r * Nx + bn + tx * 4] = v;
    }
}

// ---------------------------------------------------------------------------
// Flash-attention (fp32, causal). One CTA = one (b,h) x 64-query tile.
// 256 threads as 16(ty) x 16(tx); thread owns 4 rows (r=ty*4+rr) x
// 4 cols (j or d = tx+16*k). Q/K stored transposed at stride 65
// (conflict-free S loop); V/P at stride 68 (conflict-free PV loop).
// ---------------------------------------------------------------------------
__global__ __launch_bounds__(256)
void attn_kernel(const float* __restrict__ qkv, float* __restrict__ y)
{
    extern __shared__ float sm[];
    float* Qs = sm;                 // [64 d][65]  (transposed, scaled)
    float* Ks = Qs + 64 * 65;       // [64 d][65]  (transposed)
    float* Vs = Ks + 64 * 65;       // [64 j][68]
    float* Ps = Vs + 64 * 68;       // [64 r][68]

    const int tid = threadIdx.x;
    const int tx  = tid & 15;
    const int ty  = tid >> 4;
    const int qt  = (int)gridDim.x - 1 - (int)blockIdx.x;  // longest CTAs first
    const int bh  = blockIdx.y;
    const int b   = bh >> 4;
    const int h   = bh & 15;
    const float scale = 0.125f;     // 1/sqrt(64)

    const float* qbase = qkv + (size_t)(b * SEQ) * (3 * CH) + h * HD;
    const float* kbase = qbase + CH;
    const float* vbase = qbase + 2 * CH;

    // Load Q tile (64x64), transposed + pre-scaled
    #pragma unroll
    for (int t = 0; t < 4; t++) {
        int f   = tid + t * 256;        // 0..1023
        int row = f >> 4;
        int c4  = (f & 15) * 4;
        float4 v = *(const float4*)&qbase[(size_t)(qt * 64 + row) * (3 * CH) + c4];
        Qs[(c4 + 0) * 65 + row] = v.x * scale;
        Qs[(c4 + 1) * 65 + row] = v.y * scale;
        Qs[(c4 + 2) * 65 + row] = v.z * scale;
        Qs[(c4 + 3) * 65 + row] = v.w * scale;
    }

    float o[4][4] = {};
    float m[4], l[4];
    #pragma unroll
    for (int rr = 0; rr < 4; rr++) { m[rr] = -1e30f; l[rr] = 0.f; }

    for (int kt = 0; kt <= qt; kt++) {
        __syncthreads();   // prev iter done reading Ks/Vs/Ps; Q stores visible
        // Load K (transposed) and V tiles
        #pragma unroll
        for (int t = 0; t < 4; t++) {
            int f   = tid + t * 256;
            int row = f >> 4;
            int c4  = (f & 15) * 4;
            float4 kv = *(const float4*)&kbase[(size_t)(kt * 64 + row) * (3 * CH) + c4];
            Ks[(c4 + 0) * 65 + row] = kv.x;
            Ks[(c4 + 1) * 65 + row] = kv.y;
            Ks[(c4 + 2) * 65 + row] = kv.z;
            Ks[(c4 + 3) * 65 + row] = kv.w;
            float4 vv = *(const float4*)&vbase[(size_t)(kt * 64 + row) * (3 * CH) + c4];
            *(float4*)&Vs[row * 68 + c4] = vv;
        }
        __syncthreads();

        // S = (Q*scale) @ K^T  -- 4x4 per thread
        float s[4][4] = {};
        for (int kk = 0; kk < 64; kk++) {
            float qv[4], kv[4];
            #pragma unroll
            for (int rr = 0; rr < 4; rr++) qv[rr] = Qs[kk * 65 + ty * 4 + rr];
            #pragma unroll
            for (int jj = 0; jj < 4; jj++) kv[jj] = Ks[kk * 65 + tx + 16 * jj];
            #pragma unroll
            for (int rr = 0; rr < 4; rr++)
                #pragma unroll
                for (int jj = 0; jj < 4; jj++)
                    s[rr][jj] += qv[rr] * kv[jj];
        }

        // Causal mask on diagonal tile
        if (kt == qt) {
            #pragma unroll
            for (int rr = 0; rr < 4; rr++) {
                int i = ty * 4 + rr;
                #pragma unroll
                for (int jj = 0; jj < 4; jj++)
                    if (tx + 16 * jj > i) s[rr][jj] = -1e30f;
            }
        }

        // Online softmax (row spread over 16 tx threads; shfl over aligned 16-group)
        float alpha[4];
        #pragma unroll
        for (int rr = 0; rr < 4; rr++) {
            float mx = s[rr][0];
            #pragma unroll
            for (int jj = 1; jj < 4; jj++) mx = fmaxf(mx, s[rr][jj]);
            #pragma unroll
            for (int off = 8; off >= 1; off >>= 1)
                mx = fmaxf(mx, __shfl_xor_sync(0xffffffffu, mx, off));
            float mnew = fmaxf(m[rr], mx);
            alpha[rr] = __expf(m[rr] - mnew);
            float sum = 0.f;
            #pragma unroll
            for (int jj = 0; jj < 4; jj++) {
                float p = __expf(s[rr][jj] - mnew);
                s[rr][jj] = p;
                sum += p;
            }
            #pragma unroll
            for (int off = 8; off >= 1; off >>= 1)
                sum += __shfl_xor_sync(0xffffffffu, sum, off);
            l[rr] = l[rr] * alpha[rr] + sum;
            m[rr] = mnew;
        }

        // Write P, rescale O
        #pragma unroll
        for (int rr = 0; rr < 4; rr++)
            #pragma unroll
            for (int jj = 0; jj < 4; jj++)
                Ps[(ty * 4 + rr) * 68 + tx + 16 * jj] = s[rr][jj];
        #pragma unroll
        for (int rr = 0; rr < 4; rr++)
            #pragma unroll
            for (int dd = 0; dd < 4; dd++)
                o[rr][dd] *= alpha[rr];
        __syncthreads();   // all P writes visible before PV

        // O += P @ V
        for (int j = 0; j < 64; j++) {
            float pv[4], vv[4];
            #pragma unroll
            for (int rr = 0; rr < 4; rr++) pv[rr] = Ps[(ty * 4 + rr) * 68 + j];
            #pragma unroll
            for (int dd = 0; dd < 4; dd++) vv[dd] = Vs[j * 68 + tx + 16 * dd];
            #pragma unroll
            for (int rr = 0; rr < 4; rr++)
                #pragma unroll
                for (int dd = 0; dd < 4; dd++)
                    o[rr][dd] += pv[rr] * vv[dd];
        }
    }

    // Normalize + write y[b, t, h, d]
    #pragma unroll
    for (int rr = 0; rr < 4; rr++) {
        int row = qt * 64 + ty * 4 + rr;
        float inv = 1.0f / l[rr];
        #pragma unroll
        for (int dd = 0; dd < 4; dd++) {
            int d = tx + 16 * dd;
            y[(size_t)(b * SEQ + row) * CH + h * HD + d] = o[rr][dd] * inv;
        }
    }
}

// ---------------------------------------------------------------------------

static constexpr int ATTN_SMEM = (64 * 65 + 64 * 65 + 64 * 68 + 64 * 68) * 4; // 68096 B

extern "C" void kernel_launch(void* const* d_in, const int* in_sizes, int n_in,
                              void* d_out, int out_size)
{
    (void)in_sizes; (void)n_in; (void)out_size;
    const float* x     = (const float*)d_in[0];
    const float* w_qkv = (const float*)d_in[1];
    const float* w_out = (const float*)d_in[2];
    const float* b_out = (const float*)d_in[3];
    float* out = (float*)d_out;

    float* qkv = nullptr;
    float* y   = nullptr;
    cudaGetSymbolAddress((void**)&qkv, g_qkv);
    cudaGetSymbolAddress((void**)&y,   g_y);

    cudaFuncSetAttribute(attn_kernel,
                         cudaFuncAttributeMaxDynamicSharedMemorySize, ATTN_SMEM);

    // 1) qkv = x @ w_qkv             [4096,1024] @ [1024,3072]
    sgemm_kernel<false><<<dim3(3 * CH / 64, MROWS / 128), 256>>>(
        x, w_qkv, nullptr, qkv, MROWS, 3 * CH, CH);

    // 2) causal flash attention      -> y [4096,1024]
    attn_kernel<<<dim3(SEQ / 64, BATCH * NH), 256, ATTN_SMEM>>>(qkv, y);

    // 3) out = y @ w_out + b_out     [4096,1024] @ [1024,1024]
    sgemm_kernel<true><<<dim3(CH / 64, MROWS / 128), 256>>>(
        y, w_out, b_out, out, MROWS, CH, CH);
}

// round 7
// speedup vs baseline: 2.4551x; 2.4551x over previous
#include <cuda_runtime.h>
#include <cstdint>

#define BATCH 2
#define SEQ   2048
#define CH    1024
#define NH    16
#define HD    64
#define MROWS (BATCH*SEQ)   /* 4096 */

// Scratch (allocation-free rule: __device__ globals)
__device__ float g_qkv[MROWS * 3 * CH];   // [4096, 3072]
__device__ float g_y  [MROWS * CH];       // [4096, 1024]

// ---------------------------------------------------------------------------
// TF32 helpers
// ---------------------------------------------------------------------------
__device__ __forceinline__ uint32_t to_tf32_bits(float x) {
    uint32_t y;
    asm("cvt.rna.tf32.f32 %0, %1;" : "=r"(y) : "f"(x));
    return y;
}
__device__ __forceinline__ float to_tf32(float x) {
    return __uint_as_float(to_tf32_bits(x));
}

__device__ __forceinline__ void mma_tf32(float c[4], const float a[4], const float b[2]) {
    asm volatile(
        "mma.sync.aligned.m16n8k8.row.col.f32.tf32.tf32.f32 "
        "{%0,%1,%2,%3}, {%4,%5,%6,%7}, {%8,%9}, {%0,%1,%2,%3};"
        : "+f"(c[0]), "+f"(c[1]), "+f"(c[2]), "+f"(c[3])
        : "r"(__float_as_uint(a[0])), "r"(__float_as_uint(a[1])),
          "r"(__float_as_uint(a[2])), "r"(__float_as_uint(a[3])),
          "r"(__float_as_uint(b[0])), "r"(__float_as_uint(b[1])));
}

// ---------------------------------------------------------------------------
// TF32 tensor-core GEMM: C = A(MxK) @ B(KxN) (+bias), row-major.
// BM=128, BN=128, BK=32. 256 threads = 8 warps (2m x 4n), warp tile 64x32.
// ---------------------------------------------------------------------------
template<bool HAS_BIAS>
__global__ __launch_bounds__(256)
void gemm_tf32_kernel(const float* __restrict__ A, const float* __restrict__ B,
                      const float* __restrict__ bias, float* __restrict__ Cmat,
                      int Mx, int Nx, int Kx)
{
    constexpr int BM = 128, BN = 128, BK = 32;
    constexpr int ASTR = 36, BSTR = 132;
    __shared__ float As[BM * ASTR];   // [m][k] pad 4
    __shared__ float Bs[BK * BSTR];   // [k][n] pad 4

    const int tid  = threadIdx.x;
    const int lane = tid & 31;
    const int wid  = tid >> 5;
    const int wm   = wid >> 2;
    const int wn   = wid & 3;
    const int grp  = lane >> 2;
    const int qid  = lane & 3;
    const int bm = blockIdx.y * BM;
    const int bn = blockIdx.x * BN;

    const int a_row = tid >> 3, a_k4 = (tid & 7) * 4;
    const int b_row = tid >> 5, b_n4 = (tid & 31) * 4;

    const float* Aptr = A + (size_t)(bm + a_row) * Kx + a_k4;
    const float* Bptr = B + (size_t)b_row * Nx + bn + b_n4;

    float4 a_pf[4], b_pf[4];
    #pragma unroll
    for (int t = 0; t < 4; t++) {
        a_pf[t] = *(const float4*)(Aptr + (size_t)(t * 32) * Kx);
        b_pf[t] = *(const float4*)(Bptr + (size_t)(t * 8) * Nx);
    }

    float acc[4][4][4];
    #pragma unroll
    for (int i = 0; i < 4; i++)
        #pragma unroll
        for (int j = 0; j < 4; j++)
            #pragma unroll
            for (int c = 0; c < 4; c++) acc[i][j][c] = 0.f;

    const int ntiles = Kx / BK;
    for (int kt = 0; kt < ntiles; kt++) {
        #pragma unroll
        for (int t = 0; t < 4; t++) {
            uint4 v;
            v.x = to_tf32_bits(a_pf[t].x); v.y = to_tf32_bits(a_pf[t].y);
            v.z = to_tf32_bits(a_pf[t].z); v.w = to_tf32_bits(a_pf[t].w);
            *(uint4*)&As[(a_row + t * 32) * ASTR + a_k4] = v;
            uint4 w;
            w.x = to_tf32_bits(b_pf[t].x); w.y = to_tf32_bits(b_pf[t].y);
            w.z = to_tf32_bits(b_pf[t].z); w.w = to_tf32_bits(b_pf[t].w);
            *(uint4*)&Bs[(b_row + t * 8) * BSTR + b_n4] = w;
        }
        __syncthreads();

        if (kt + 1 < ntiles) {
            const float* An = Aptr + (kt + 1) * BK;
            const float* Bn = Bptr + (size_t)(kt + 1) * BK * Nx;
            #pragma unroll
            for (int t = 0; t < 4; t++) {
                a_pf[t] = *(const float4*)(An + (size_t)(t * 32) * Kx);
                b_pf[t] = *(const float4*)(Bn + (size_t)(t * 8) * Nx);
            }
        }

        #pragma unroll
        for (int s = 0; s < 4; s++) {
            const int k0 = s * 8;
            float afr[4][4], bfr[4][2];
            #pragma unroll
            for (int mt = 0; mt < 4; mt++) {
                int rb = wm * 64 + mt * 16 + grp;
                afr[mt][0] = As[(rb    ) * ASTR + k0 + qid    ];
                afr[mt][1] = As[(rb + 8) * ASTR + k0 + qid    ];
                afr[mt][2] = As[(rb    ) * ASTR + k0 + qid + 4];
                afr[mt][3] = As[(rb + 8) * ASTR + k0 + qid + 4];
            }
            #pragma unroll
            for (int nt = 0; nt < 4; nt++) {
                int cb = wn * 32 + nt * 8 + grp;
                bfr[nt][0] = Bs[(k0 + qid    ) * BSTR + cb];
                bfr[nt][1] = Bs[(k0 + qid + 4) * BSTR + cb];
            }
            #pragma unroll
            for (int mt = 0; mt < 4; mt++)
                #pragma unroll
                for (int nt = 0; nt < 4; nt++)
                    mma_tf32(acc[mt][nt], afr[mt], bfr[nt]);
        }
        __syncthreads();
    }

    #pragma unroll
    for (int mt = 0; mt < 4; mt++) {
        #pragma unroll
        for (int nt = 0; nt < 4; nt++) {
            int row = bm + wm * 64 + mt * 16 + grp;
            int col = bn + wn * 32 + nt * 8 + qid * 2;
            float2 v0 = make_float2(acc[mt][nt][0], acc[mt][nt][1]);
            float2 v1 = make_float2(acc[mt][nt][2], acc[mt][nt][3]);
            if (HAS_BIAS) {
                float2 bb = *(const float2*)&bias[col];
                v0.x += bb.x; v0.y += bb.y;
                v1.x += bb.x; v1.y += bb.y;
            }
            *(float2*)&Cmat[(size_t)row * Nx + col]       = v0;
            *(float2*)&Cmat[(size_t)(row + 8) * Nx + col] = v1;
        }
    }
}

// ---------------------------------------------------------------------------
// MMA flash-attention (tf32, causal). CTA = 64 queries x (b,h); 4 warps,
// warp w owns S/O rows [16w, 16w+16). K-tiles of 64. m16n8k8 for both
// S = Q@K^T (A=Q row-major [q][d], B=K row-major [j][d]) and
// O += P@V   (A=P row-major [q][j], B=V^T stored as Vt[d][j]).
// Softmax on C-fragment registers: row r -> lanes {4*grp..4*grp+3},
// reduce with shfl_xor 1,2. P routed via per-warp smem (C-frag cols 2qid
// don't match A-frag k qid/qid+4). All strides 68 -> frag reads hit banks
// (4*grp+qid): conflict-free.
// ---------------------------------------------------------------------------
__global__ __launch_bounds__(128)
void attn_mma_kernel(const float* __restrict__ qkv, float* __restrict__ y)
{
    constexpr int STR = 68;
    extern __shared__ float sm[];
    float* Qs = sm;                  // [64 q][68]  tf32 bits, pre-scaled
    float* Ks = Qs + 64 * STR;       // [64 j][68]  tf32 bits
    float* Vt = Ks + 64 * STR;       // [64 d][68]  (transposed V), tf32 bits
    float* Ps = Vt + 64 * STR;       // [4 warps][16 r][68]

    const int tid  = threadIdx.x;
    const int lane = tid & 31;
    const int w    = tid >> 5;       // 0..3
    const int grp  = lane >> 2;      // 0..7
    const int qid  = lane & 3;       // 0..3
    const int qt   = (int)gridDim.x - 1 - (int)blockIdx.x;  // longest first
    const int bh   = blockIdx.y;
    const int b    = bh >> 4;
    const int h    = bh & 15;
    const float scale = 0.125f;      // 1/sqrt(64)

    const float* qbase = qkv + (size_t)(b * SEQ) * (3 * CH) + h * HD;
    const float* kbase = qbase + CH;
    const float* vbase = qbase + 2 * CH;

    float* Pw = Ps + w * 16 * STR;   // this warp's P block

    // Load Q tile 64x64 (8 float4 per thread), scale + tf32, [q][d]
    #pragma unroll
    for (int t = 0; t < 8; t++) {
        int f   = tid + t * 128;     // 0..1023
        int row = f >> 4;
        int c4  = (f & 15) * 4;
        float4 v = *(const float4*)&qbase[(size_t)(qt * 64 + row) * (3 * CH) + c4];
        uint4 u;
        u.x = to_tf32_bits(v.x * scale); u.y = to_tf32_bits(v.y * scale);
        u.z = to_tf32_bits(v.z * scale); u.w = to_tf32_bits(v.w * scale);
        *(uint4*)&Qs[row * STR + c4] = u;
    }

    float o[8][4];
    #pragma unroll
    for (int nt = 0; nt < 8; nt++)
        #pragma unroll
        for (int c = 0; c < 4; c++) o[nt][c] = 0.f;
    float m0 = -1e30f, m1 = -1e30f, l0 = 0.f, l1 = 0.f;

    const int row0 = 16 * w + grp;       // local S-row for c0,c1
    const int row1 = row0 + 8;           // local S-row for c2,c3

    for (int kt = 0; kt <= qt; kt++) {
        __syncthreads();   // prev iter done reading Ks/Vt; Qs stores visible (kt=0)
        // Load K tile [j][d] and V transposed [d][j]
        #pragma unroll
        for (int t = 0; t < 8; t++) {
            int f   = tid + t * 128;
            int row = f >> 4;
            int c4  = (f & 15) * 4;
            float4 kv = *(const float4*)&kbase[(size_t)(kt * 64 + row) * (3 * CH) + c4];
            uint4 u;
            u.x = to_tf32_bits(kv.x); u.y = to_tf32_bits(kv.y);
            u.z = to_tf32_bits(kv.z); u.w = to_tf32_bits(kv.w);
            *(uint4*)&Ks[row * STR + c4] = u;
            float4 vv = *(const float4*)&vbase[(size_t)(kt * 64 + row) * (3 * CH) + c4];
            Vt[(c4 + 0) * STR + row] = to_tf32(vv.x);
            Vt[(c4 + 1) * STR + row] = to_tf32(vv.y);
            Vt[(c4 + 2) * STR + row] = to_tf32(vv.z);
            Vt[(c4 + 3) * STR + row] = to_tf32(vv.w);
        }
        __syncthreads();

        // ---- S = Q @ K^T : warp computes 16x64, 8 n-tiles x 8 k-steps
        float sfr[8][4];
        #pragma unroll
        for (int nt = 0; nt < 8; nt++)
            #pragma unroll
            for (int c = 0; c < 4; c++) sfr[nt][c] = 0.f;

        #pragma unroll
        for (int s = 0; s < 8; s++) {
            const int k0 = s * 8;
            float afr[4];
            afr[0] = Qs[row0 * STR + k0 + qid    ];
            afr[1] = Qs[row1 * STR + k0 + qid    ];
            afr[2] = Qs[row0 * STR + k0 + qid + 4];
            afr[3] = Qs[row1 * STR + k0 + qid + 4];
            #pragma unroll
            for (int nt = 0; nt < 8; nt++) {
                float bfr[2];
                bfr[0] = Ks[(nt * 8 + grp) * STR + k0 + qid    ];
                bfr[1] = Ks[(nt * 8 + grp) * STR + k0 + qid + 4];
                mma_tf32(sfr[nt], afr, bfr);
            }
        }

        // ---- causal mask on diagonal tile (cols j = 8nt+2qid+{0,1})
        if (kt == qt) {
            #pragma unroll
            for (int nt = 0; nt < 8; nt++) {
                int j0 = nt * 8 + qid * 2;
                if (j0     > row0) sfr[nt][0] = -1e30f;
                if (j0 + 1 > row0) sfr[nt][1] = -1e30f;
                if (j0     > row1) sfr[nt][2] = -1e30f;
                if (j0 + 1 > row1) sfr[nt][3] = -1e30f;
            }
        }

        // ---- online softmax (rows row0, row1; quad reduction)
        float mx0 = -1e30f, mx1 = -1e30f;
        #pragma unroll
        for (int nt = 0; nt < 8; nt++) {
            mx0 = fmaxf(mx0, fmaxf(sfr[nt][0], sfr[nt][1]));
            mx1 = fmaxf(mx1, fmaxf(sfr[nt][2], sfr[nt][3]));
        }
        #pragma unroll
        for (int off = 1; off <= 2; off <<= 1) {
            mx0 = fmaxf(mx0, __shfl_xor_sync(0xffffffffu, mx0, off));
            mx1 = fmaxf(mx1, __shfl_xor_sync(0xffffffffu, mx1, off));
        }
        float mnew0 = fmaxf(m0, mx0), mnew1 = fmaxf(m1, mx1);
        float alpha0 = __expf(m0 - mnew0), alpha1 = __expf(m1 - mnew1);
        float sum0 = 0.f, sum1 = 0.f;
        #pragma unroll
        for (int nt = 0; nt < 8; nt++) {
            sfr[nt][0] = __expf(sfr[nt][0] - mnew0);
            sfr[nt][1] = __expf(sfr[nt][1] - mnew0);
            sfr[nt][2] = __expf(sfr[nt][2] - mnew1);
            sfr[nt][3] = __expf(sfr[nt][3] - mnew1);
            sum0 += sfr[nt][0] + sfr[nt][1];
            sum1 += sfr[nt][2] + sfr[nt][3];
        }
        #pragma unroll
        for (int off = 1; off <= 2; off <<= 1) {
            sum0 += __shfl_xor_sync(0xffffffffu, sum0, off);
            sum1 += __shfl_xor_sync(0xffffffffu, sum1, off);
        }
        l0 = l0 * alpha0 + sum0;  m0 = mnew0;
        l1 = l1 * alpha1 + sum1;  m1 = mnew1;

        // ---- write P (tf32) to per-warp smem; rescale O
        #pragma unroll
        for (int nt = 0; nt < 8; nt++) {
            int cc = nt * 8 + qid * 2;
            float2 p0 = make_float2(to_tf32(sfr[nt][0]), to_tf32(sfr[nt][1]));
            float2 p1 = make_float2(to_tf32(sfr[nt][2]), to_tf32(sfr[nt][3]));
            *(float2*)&Pw[(grp    ) * STR + cc] = p0;
            *(float2*)&Pw[(grp + 8) * STR + cc] = p1;
            o[nt][0] *= alpha0; o[nt][1] *= alpha0;
            o[nt][2] *= alpha1; o[nt][3] *= alpha1;
        }
        __syncwarp();

        // ---- O += P @ V  (A = Pw [r][j], B = Vt [d][j])
        #pragma unroll
        for (int s = 0; s < 8; s++) {
            const int k0 = s * 8;
            float afr[4];
            afr[0] = Pw[(grp    ) * STR + k0 + qid    ];
            afr[1] = Pw[(grp + 8) * STR + k0 + qid    ];
            afr[2] = Pw[(grp    ) * STR + k0 + qid + 4];
            afr[3] = Pw[(grp + 8) * STR + k0 + qid + 4];
            #pragma unroll
            for (int nt = 0; nt < 8; nt++) {
                float bfr[2];
                bfr[0] = Vt[(nt * 8 + grp) * STR + k0 + qid    ];
                bfr[1] = Vt[(nt * 8 + grp) * STR + k0 + qid + 4];
                mma_tf32(o[nt], afr, bfr);
            }
        }
        __syncwarp();   // done reading Pw before next iteration overwrites
    }

    // ---- normalize + write y[b, t, h, d]; cols d = 8nt + 2qid + {0,1}
    float inv0 = 1.0f / l0, inv1 = 1.0f / l1;
    int gr0 = qt * 64 + row0, gr1 = qt * 64 + row1;
    #pragma unroll
    for (int nt = 0; nt < 8; nt++) {
        int d = nt * 8 + qid * 2;
        float2 v0 = make_float2(o[nt][0] * inv0, o[nt][1] * inv0);
        float2 v1 = make_float2(o[nt][2] * inv1, o[nt][3] * inv1);
        *(float2*)&y[(size_t)(b * SEQ + gr0) * CH + h * HD + d] = v0;
        *(float2*)&y[(size_t)(b * SEQ + gr1) * CH + h * HD + d] = v1;
    }
}

// ---------------------------------------------------------------------------

static constexpr int ATTN_SMEM = (64 * 68 * 3 + 4 * 16 * 68) * 4;  // 69632 B

extern "C" void kernel_launch(void* const* d_in, const int* in_sizes, int n_in,
                              void* d_out, int out_size)
{
    (void)in_sizes; (void)n_in; (void)out_size;
    const float* x     = (const float*)d_in[0];
    const float* w_qkv = (const float*)d_in[1];
    const float* w_out = (const float*)d_in[2];
    const float* b_out = (const float*)d_in[3];
    float* out = (float*)d_out;

    float* qkv = nullptr;
    float* y   = nullptr;
    cudaGetSymbolAddress((void**)&qkv, g_qkv);
    cudaGetSymbolAddress((void**)&y,   g_y);

    cudaFuncSetAttribute(attn_mma_kernel,
                         cudaFuncAttributeMaxDynamicSharedMemorySize, ATTN_SMEM);

    // 1) qkv = x @ w_qkv             [4096,1024] @ [1024,3072]  (tf32 TC)
    gemm_tf32_kernel<false><<<dim3(3 * CH / 128, MROWS / 128), 256>>>(
        x, w_qkv, nullptr, qkv, MROWS, 3 * CH, CH);

    // 2) causal flash attention      -> y [4096,1024]  (tf32 TC)
    attn_mma_kernel<<<dim3(SEQ / 64, BATCH * NH), 128, ATTN_SMEM>>>(qkv, y);

    // 3) out = y @ w_out + b_out     [4096,1024] @ [1024,1024]  (tf32 TC)
    gemm_tf32_kernel<true><<<dim3(CH / 128, MROWS / 128), 256>>>(
        y, w_out, b_out, out, MROWS, CH, CH);
}

// round 8
// speedup vs baseline: 2.4776x; 1.0092x over previous
#include <cuda_runtime.h>
#include <cstdint>

#define BATCH 2
#define SEQ   2048
#define CH    1024
#define NH    16
#define HD    64
#define MROWS (BATCH*SEQ)   /* 4096 */

// Scratch (allocation-free rule: __device__ globals)
__device__ float g_qkv[MROWS * 3 * CH];   // tf32-rounded qkv
__device__ float g_y  [MROWS * CH];       // tf32-rounded attn out
__device__ float g_x  [MROWS * CH];       // tf32-rounded x
__device__ float g_wq [CH * 3 * CH];      // tf32-rounded w_qkv
__device__ float g_wo [CH * CH];          // tf32-rounded w_out

// ---------------------------------------------------------------------------
// TF32 + cp.async helpers
// ---------------------------------------------------------------------------
__device__ __forceinline__ uint32_t to_tf32_bits(float x) {
    uint32_t y;
    asm("cvt.rna.tf32.f32 %0, %1;" : "=r"(y) : "f"(x));
    return y;
}
__device__ __forceinline__ float to_tf32(float x) {
    return __uint_as_float(to_tf32_bits(x));
}

__device__ __forceinline__ void mma_tf32(float c[4], const float a[4], const float b[2]) {
    asm volatile(
        "mma.sync.aligned.m16n8k8.row.col.f32.tf32.tf32.f32 "
        "{%0,%1,%2,%3}, {%4,%5,%6,%7}, {%8,%9}, {%0,%1,%2,%3};"
        : "+f"(c[0]), "+f"(c[1]), "+f"(c[2]), "+f"(c[3])
        : "r"(__float_as_uint(a[0])), "r"(__float_as_uint(a[1])),
          "r"(__float_as_uint(a[2])), "r"(__float_as_uint(a[3])),
          "r"(__float_as_uint(b[0])), "r"(__float_as_uint(b[1])));
}

__device__ __forceinline__ void cp_async16(uint32_t saddr, const void* gptr) {
    asm volatile("cp.async.cg.shared.global [%0], [%1], 16;" :: "r"(saddr), "l"(gptr));
}
__device__ __forceinline__ void cp_commit() {
    asm volatile("cp.async.commit_group;");
}
__device__ __forceinline__ void cp_wait0() {
    asm volatile("cp.async.wait_group 0;");
}

// ---------------------------------------------------------------------------
// Elementwise tf32 rounding (float4 granularity)
// ---------------------------------------------------------------------------
__global__ void cvt_tf32_kernel(const float4* __restrict__ in, float4* __restrict__ out, int n4)
{
    int i = blockIdx.x * blockDim.x + threadIdx.x;
    if (i < n4) {
        float4 v = in[i];
        v.x = to_tf32(v.x); v.y = to_tf32(v.y);
        v.z = to_tf32(v.z); v.w = to_tf32(v.w);
        out[i] = v;
    }
}

// ---------------------------------------------------------------------------
// TF32 tensor-core GEMM, cp.async double-buffered.
// C = A(MxK) @ B(KxN) (+bias). A,B already tf32-rounded (raw bits fed to MMA).
// BM=128, BN=128, BK=32. 256 threads = 8 warps (2m x 4n), warp tile 64x32.
// 2 CTAs/SM (smem 70656 B, regs capped by launch_bounds).
// ---------------------------------------------------------------------------
template<bool HAS_BIAS, bool ROUND_OUT>
__global__ __launch_bounds__(256, 2)
void gemm_tf32_kernel(const float* __restrict__ A, const float* __restrict__ B,
                      const float* __restrict__ bias, float* __restrict__ Cmat,
                      int Mx, int Nx, int Kx)
{
    constexpr int BM = 128, BN = 128, BK = 32;
    constexpr int ASTR = 36, BSTR = 132;
    constexpr int ASZ = BM * ASTR, BSZ = BK * BSTR;
    extern __shared__ float smem[];
    float* Asb[2] = { smem, smem + ASZ };
    float* Bsb[2] = { smem + 2 * ASZ, smem + 2 * ASZ + BSZ };

    const int tid  = threadIdx.x;
    const int lane = tid & 31;
    const int wid  = tid >> 5;
    const int wm   = wid >> 2;
    const int wn   = wid & 3;
    const int grp  = lane >> 2;
    const int qid  = lane & 3;
    const int bm = blockIdx.y * BM;
    const int bn = blockIdx.x * BN;

    const int a_row = tid >> 3, a_k4 = (tid & 7) * 4;
    const int b_row = tid >> 5, b_n4 = (tid & 31) * 4;

    const float* Aptr = A + (size_t)(bm + a_row) * Kx + a_k4;
    const float* Bptr = B + (size_t)b_row * Nx + bn + b_n4;

    uint32_t sA[2], sB[2];
    sA[0] = (uint32_t)__cvta_generic_to_shared(Asb[0] + a_row * ASTR + a_k4);
    sA[1] = (uint32_t)__cvta_generic_to_shared(Asb[1] + a_row * ASTR + a_k4);
    sB[0] = (uint32_t)__cvta_generic_to_shared(Bsb[0] + b_row * BSTR + b_n4);
    sB[1] = (uint32_t)__cvta_generic_to_shared(Bsb[1] + b_row * BSTR + b_n4);

    const int ntiles = Kx / BK;

    // issue tile kt into buffer buf
    auto issue = [&](int kt, int buf) {
        const float* Ag = Aptr + kt * BK;
        const float* Bg = Bptr + (size_t)kt * BK * Nx;
        #pragma unroll
        for (int t = 0; t < 4; t++)
            cp_async16(sA[buf] + t * (32 * ASTR * 4), Ag + (size_t)(t * 32) * Kx);
        #pragma unroll
        for (int t = 0; t < 4; t++)
            cp_async16(sB[buf] + t * (8 * BSTR * 4), Bg + (size_t)(t * 8) * Nx);
        cp_commit();
    };

    float acc[4][4][4];
    #pragma unroll
    for (int i = 0; i < 4; i++)
        #pragma unroll
        for (int j = 0; j < 4; j++)
            #pragma unroll
            for (int c = 0; c < 4; c++) acc[i][j][c] = 0.f;

    issue(0, 0);

    for (int kt = 0; kt < ntiles; kt++) {
        cp_wait0();
        __syncthreads();   // tile kt visible; prev compute done before reuse
        if (kt + 1 < ntiles) issue(kt + 1, (kt + 1) & 1);

        const float* As_ = Asb[kt & 1];
        const float* Bs_ = Bsb[kt & 1];
        #pragma unroll
        for (int s = 0; s < 4; s++) {
            const int k0 = s * 8;
            float afr[4][4], bfr[4][2];
            #pragma unroll
            for (int mt = 0; mt < 4; mt++) {
                int rb = wm * 64 + mt * 16 + grp;
                afr[mt][0] = As_[(rb    ) * ASTR + k0 + qid    ];
                afr[mt][1] = As_[(rb + 8) * ASTR + k0 + qid    ];
                afr[mt][2] = As_[(rb    ) * ASTR + k0 + qid + 4];
                afr[mt][3] = As_[(rb + 8) * ASTR + k0 + qid + 4];
            }
            #pragma unroll
            for (int nt = 0; nt < 4; nt++) {
                int cb = wn * 32 + nt * 8 + grp;
                bfr[nt][0] = Bs_[(k0 + qid    ) * BSTR + cb];
                bfr[nt][1] = Bs_[(k0 + qid + 4) * BSTR + cb];
            }
            #pragma unroll
            for (int mt = 0; mt < 4; mt++)
                #pragma unroll
                for (int nt = 0; nt < 4; nt++)
                    mma_tf32(acc[mt][nt], afr[mt], bfr[nt]);
        }
    }

    #pragma unroll
    for (int mt = 0; mt < 4; mt++) {
        #pragma unroll
        for (int nt = 0; nt < 4; nt++) {
            int row = bm + wm * 64 + mt * 16 + grp;
            int col = bn + wn * 32 + nt * 8 + qid * 2;
            float2 v0 = make_float2(acc[mt][nt][0], acc[mt][nt][1]);
            float2 v1 = make_float2(acc[mt][nt][2], acc[mt][nt][3]);
            if (HAS_BIAS) {
                float2 bb = *(const float2*)&bias[col];
                v0.x += bb.x; v0.y += bb.y;
                v1.x += bb.x; v1.y += bb.y;
            }
            if (ROUND_OUT) {
                v0.x = to_tf32(v0.x); v0.y = to_tf32(v0.y);
                v1.x = to_tf32(v1.x); v1.y = to_tf32(v1.y);
            }
            *(float2*)&Cmat[(size_t)row * Nx + col]       = v0;
            *(float2*)&Cmat[(size_t)(row + 8) * Nx + col] = v1;
        }
    }
}

// ---------------------------------------------------------------------------
// MMA flash-attention (tf32, causal). CTA = 64 queries x (b,h); 4 warps.
// Input qkv is already tf32-rounded -> no conversions on load.
// Output y rounded to tf32 (feeds tf32 GEMM2; bit-identical to converting
// at GEMM2's smem store).
// ---------------------------------------------------------------------------
__global__ __launch_bounds__(128)
void attn_mma_kernel(const float* __restrict__ qkv, float* __restrict__ y)
{
    constexpr int STR = 68;
    extern __shared__ float sm[];
    float* Qs = sm;                  // [64 q][68]  pre-scaled
    float* Ks = Qs + 64 * STR;       // [64 j][68]
    float* Vt = Ks + 64 * STR;       // [64 d][68]  (transposed V)
    float* Ps = Vt + 64 * STR;       // [4 warps][16 r][68]

    const int tid  = threadIdx.x;
    const int lane = tid & 31;
    const int w    = tid >> 5;
    const int grp  = lane >> 2;
    const int qid  = lane & 3;
    const int qt   = (int)gridDim.x - 1 - (int)blockIdx.x;  // longest first
    const int bh   = blockIdx.y;
    const int b    = bh >> 4;
    const int h    = bh & 15;
    const float scale = 0.125f;      // 1/sqrt(64): exact exponent shift in tf32

    const float* qbase = qkv + (size_t)(b * SEQ) * (3 * CH) + h * HD;
    const float* kbase = qbase + CH;
    const float* vbase = qbase + 2 * CH;

    float* Pw = Ps + w * 16 * STR;

    // Load Q tile 64x64 (8 float4 per thread), scale (exact), [q][d]
    #pragma unroll
    for (int t = 0; t < 8; t++) {
        int f   = tid + t * 128;
        int row = f >> 4;
        int c4  = (f & 15) * 4;
        float4 v = *(const float4*)&qbase[(size_t)(qt * 64 + row) * (3 * CH) + c4];
        v.x *= scale; v.y *= scale; v.z *= scale; v.w *= scale;
        *(float4*)&Qs[row * STR + c4] = v;
    }

    float o[8][4];
    #pragma unroll
    for (int nt = 0; nt < 8; nt++)
        #pragma unroll
        for (int c = 0; c < 4; c++) o[nt][c] = 0.f;
    float m0 = -1e30f, m1 = -1e30f, l0 = 0.f, l1 = 0.f;

    const int row0 = 16 * w + grp;
    const int row1 = row0 + 8;

    for (int kt = 0; kt <= qt; kt++) {
        __syncthreads();
        #pragma unroll
        for (int t = 0; t < 8; t++) {
            int f   = tid + t * 128;
            int row = f >> 4;
            int c4  = (f & 15) * 4;
            float4 kv = *(const float4*)&kbase[(size_t)(kt * 64 + row) * (3 * CH) + c4];
            *(float4*)&Ks[row * STR + c4] = kv;
            float4 vv = *(const float4*)&vbase[(size_t)(kt * 64 + row) * (3 * CH) + c4];
            Vt[(c4 + 0) * STR + row] = vv.x;
            Vt[(c4 + 1) * STR + row] = vv.y;
            Vt[(c4 + 2) * STR + row] = vv.z;
            Vt[(c4 + 3) * STR + row] = vv.w;
        }
        __syncthreads();

        // ---- S = Q @ K^T
        float sfr[8][4];
        #pragma unroll
        for (int nt = 0; nt < 8; nt++)
            #pragma unroll
            for (int c = 0; c < 4; c++) sfr[nt][c] = 0.f;

        #pragma unroll
        for (int s = 0; s < 8; s++) {
            const int k0 = s * 8;
            float afr[4];
            afr[0] = Qs[row0 * STR + k0 + qid    ];
            afr[1] = Qs[row1 * STR + k0 + qid    ];
            afr[2] = Qs[row0 * STR + k0 + qid + 4];
            afr[3] = Qs[row1 * STR + k0 + qid + 4];
            #pragma unroll
            for (int nt = 0; nt < 8; nt++) {
                float bfr[2];
                bfr[0] = Ks[(nt * 8 + grp) * STR + k0 + qid    ];
                bfr[1] = Ks[(nt * 8 + grp) * STR + k0 + qid + 4];
                mma_tf32(sfr[nt], afr, bfr);
            }
        }

        // ---- causal mask on diagonal tile
        if (kt == qt) {
            #pragma unroll
            for (int nt = 0; nt < 8; nt++) {
                int j0 = nt * 8 + qid * 2;
                if (j0     > row0) sfr[nt][0] = -1e30f;
                if (j0 + 1 > row0) sfr[nt][1] = -1e30f;
                if (j0     > row1) sfr[nt][2] = -1e30f;
                if (j0 + 1 > row1) sfr[nt][3] = -1e30f;
            }
        }

        // ---- online softmax
        float mx0 = -1e30f, mx1 = -1e30f;
        #pragma unroll
        for (int nt = 0; nt < 8; nt++) {
            mx0 = fmaxf(mx0, fmaxf(sfr[nt][0], sfr[nt][1]));
            mx1 = fmaxf(mx1, fmaxf(sfr[nt][2], sfr[nt][3]));
        }
        #pragma unroll
        for (int off = 1; off <= 2; off <<= 1) {
            mx0 = fmaxf(mx0, __shfl_xor_sync(0xffffffffu, mx0, off));
            mx1 = fmaxf(mx1, __shfl_xor_sync(0xffffffffu, mx1, off));
        }
        float mnew0 = fmaxf(m0, mx0), mnew1 = fmaxf(m1, mx1);
        float alpha0 = __expf(m0 - mnew0), alpha1 = __expf(m1 - mnew1);
        float sum0 = 0.f, sum1 = 0.f;
        #pragma unroll
        for (int nt = 0; nt < 8; nt++) {
            sfr[nt][0] = __expf(sfr[nt][0] - mnew0);
            sfr[nt][1] = __expf(sfr[nt][1] - mnew0);
            sfr[nt][2] = __expf(sfr[nt][2] - mnew1);
            sfr[nt][3] = __expf(sfr[nt][3] - mnew1);
            sum0 += sfr[nt][0] + sfr[nt][1];
            sum1 += sfr[nt][2] + sfr[nt][3];
        }
        #pragma unroll
        for (int off = 1; off <= 2; off <<= 1) {
            sum0 += __shfl_xor_sync(0xffffffffu, sum0, off);
            sum1 += __shfl_xor_sync(0xffffffffu, sum1, off);
        }
        l0 = l0 * alpha0 + sum0;  m0 = mnew0;
        l1 = l1 * alpha1 + sum1;  m1 = mnew1;

        // ---- write P (tf32) to per-warp smem; rescale O
        #pragma unroll
        for (int nt = 0; nt < 8; nt++) {
            int cc = nt * 8 + qid * 2;
            float2 p0 = make_float2(to_tf32(sfr[nt][0]), to_tf32(sfr[nt][1]));
            float2 p1 = make_float2(to_tf32(sfr[nt][2]), to_tf32(sfr[nt][3]));
            *(float2*)&Pw[(grp    ) * STR + cc] = p0;
            *(float2*)&Pw[(grp + 8) * STR + cc] = p1;
            o[nt][0] *= alpha0; o[nt][1] *= alpha0;
            o[nt][2] *= alpha1; o[nt][3] *= alpha1;
        }
        __syncwarp();

        // ---- O += P @ V
        #pragma unroll
        for (int s = 0; s < 8; s++) {
            const int k0 = s * 8;
            float afr[4];
            afr[0] = Pw[(grp    ) * STR + k0 + qid    ];
            afr[1] = Pw[(grp + 8) * STR + k0 + qid    ];
            afr[2] = Pw[(grp    ) * STR + k0 + qid + 4];
            afr[3] = Pw[(grp + 8) * STR + k0 + qid + 4];
            #pragma unroll
            for (int nt = 0; nt < 8; nt++) {
                float bfr[2];
                bfr[0] = Vt[(nt * 8 + grp) * STR + k0 + qid    ];
                bfr[1] = Vt[(nt * 8 + grp) * STR + k0 + qid + 4];
                mma_tf32(o[nt], afr, bfr);
            }
        }
        __syncwarp();
    }

    // ---- normalize + write y (tf32-rounded, feeds tf32 GEMM2)
    float inv0 = 1.0f / l0, inv1 = 1.0f / l1;
    int gr0 = qt * 64 + row0, gr1 = qt * 64 + row1;
    #pragma unroll
    for (int nt = 0; nt < 8; nt++) {
        int d = nt * 8 + qid * 2;
        float2 v0 = make_float2(to_tf32(o[nt][0] * inv0), to_tf32(o[nt][1] * inv0));
        float2 v1 = make_float2(to_tf32(o[nt][2] * inv1), to_tf32(o[nt][3] * inv1));
        *(float2*)&y[(size_t)(b * SEQ + gr0) * CH + h * HD + d] = v0;
        *(float2*)&y[(size_t)(b * SEQ + gr1) * CH + h * HD + d] = v1;
    }
}

// ---------------------------------------------------------------------------

static constexpr int GEMM_SMEM = (2 * 128 * 36 + 2 * 32 * 132) * 4;   // 70656 B
static constexpr int ATTN_SMEM = (64 * 68 * 3 + 4 * 16 * 68) * 4;     // 69632 B

extern "C" void kernel_launch(void* const* d_in, const int* in_sizes, int n_in,
                              void* d_out, int out_size)
{
    (void)in_sizes; (void)n_in; (void)out_size;
    const float* x     = (const float*)d_in[0];
    const float* w_qkv = (const float*)d_in[1];
    const float* w_out = (const float*)d_in[2];
    const float* b_out = (const float*)d_in[3];
    float* out = (float*)d_out;

    float *qkv, *y, *xc, *wq, *wo;
    cudaGetSymbolAddress((void**)&qkv, g_qkv);
    cudaGetSymbolAddress((void**)&y,   g_y);
    cudaGetSymbolAddress((void**)&xc,  g_x);
    cudaGetSymbolAddress((void**)&wq,  g_wq);
    cudaGetSymbolAddress((void**)&wo,  g_wo);

    cudaFuncSetAttribute(gemm_tf32_kernel<false, true>,
                         cudaFuncAttributeMaxDynamicSharedMemorySize, GEMM_SMEM);
    cudaFuncSetAttribute(gemm_tf32_kernel<true, false>,
                         cudaFuncAttributeMaxDynamicSharedMemorySize, GEMM_SMEM);
    cudaFuncSetAttribute(attn_mma_kernel,
                         cudaFuncAttributeMaxDynamicSharedMemorySize, ATTN_SMEM);

    // 0) pre-round operands to tf32 (rna), once
    cvt_tf32_kernel<<<(MROWS * CH / 4 + 255) / 256, 256>>>(
        (const float4*)x, (float4*)xc, MROWS * CH / 4);
    cvt_tf32_kernel<<<(CH * 3 * CH / 4 + 255) / 256, 256>>>(
        (const float4*)w_qkv, (float4*)wq, CH * 3 * CH / 4);
    cvt_tf32_kernel<<<(CH * CH / 4 + 255) / 256, 256>>>(
        (const float4*)w_out, (float4*)wo, CH * CH / 4);

    // 1) qkv = x @ w_qkv  (tf32 TC, cp.async), output tf32-rounded
    gemm_tf32_kernel<false, true><<<dim3(3 * CH / 128, MROWS / 128), 256, GEMM_SMEM>>>(
        xc, wq, nullptr, qkv, MROWS, 3 * CH, CH);

    // 2) causal flash attention -> y (tf32 TC), output tf32-rounded
    attn_mma_kernel<<<dim3(SEQ / 64, BATCH * NH), 128, ATTN_SMEM>>>(qkv, y);

    // 3) out = y @ w_out + b_out  (tf32 TC, cp.async), fp32 output
    gemm_tf32_kernel<true, false><<<dim3(CH / 128, MROWS / 128), 256, GEMM_SMEM>>>(
        y, wo, b_out, out, MROWS, CH, CH);
}

// round 9
// speedup vs baseline: 2.6347x; 1.0634x over previous
#include <cuda_runtime.h>
#include <cstdint>

#define BATCH 2
#define SEQ   2048
#define CH    1024
#define NH    16
#define HD    64
#define MROWS (BATCH*SEQ)   /* 4096 */

// Scratch (allocation-free rule: __device__ globals)
__device__ float g_qkv[MROWS * 3 * CH];   // tf32-rounded qkv
__device__ float g_y  [MROWS * CH];       // tf32-rounded attn out
__device__ float g_x  [MROWS * CH];       // tf32-rounded x
__device__ float g_wq [CH * 3 * CH];      // tf32-rounded w_qkv
__device__ float g_wo [CH * CH];          // tf32-rounded w_out

// ---------------------------------------------------------------------------
// TF32 / MMA / cp.async / ldmatrix helpers
// ---------------------------------------------------------------------------
__device__ __forceinline__ uint32_t to_tf32_bits(float x) {
    uint32_t y;
    asm("cvt.rna.tf32.f32 %0, %1;" : "=r"(y) : "f"(x));
    return y;
}
__device__ __forceinline__ float to_tf32(float x) {
    return __uint_as_float(to_tf32_bits(x));
}

__device__ __forceinline__ void mma_tf32(float c[4], const uint32_t a[4], const uint32_t b0, const uint32_t b1) {
    asm volatile(
        "mma.sync.aligned.m16n8k8.row.col.f32.tf32.tf32.f32 "
        "{%0,%1,%2,%3}, {%4,%5,%6,%7}, {%8,%9}, {%0,%1,%2,%3};"
        : "+f"(c[0]), "+f"(c[1]), "+f"(c[2]), "+f"(c[3])
        : "r"(a[0]), "r"(a[1]), "r"(a[2]), "r"(a[3]),
          "r"(b0), "r"(b1));
}

__device__ __forceinline__ void ldsm_x4(uint32_t r[4], uint32_t saddr) {
    asm volatile("ldmatrix.sync.aligned.m8n8.x4.shared.b16 {%0,%1,%2,%3}, [%4];"
        : "=r"(r[0]), "=r"(r[1]), "=r"(r[2]), "=r"(r[3]) : "r"(saddr));
}

__device__ __forceinline__ void cp_async16(uint32_t saddr, const void* gptr) {
    asm volatile("cp.async.cg.shared.global [%0], [%1], 16;" :: "r"(saddr), "l"(gptr));
}
__device__ __forceinline__ void cp_commit() {
    asm volatile("cp.async.commit_group;");
}
__device__ __forceinline__ void cp_wait0() {
    asm volatile("cp.async.wait_group 0;");
}

// ---------------------------------------------------------------------------
// Elementwise tf32 rounding (float4 granularity)
// ---------------------------------------------------------------------------
__global__ void cvt_tf32_kernel(const float4* __restrict__ in, float4* __restrict__ out, int n4)
{
    int i = blockIdx.x * blockDim.x + threadIdx.x;
    if (i < n4) {
        float4 v = in[i];
        v.x = to_tf32(v.x); v.y = to_tf32(v.y);
        v.z = to_tf32(v.z); v.w = to_tf32(v.w);
        out[i] = v;
    }
}

// ---------------------------------------------------------------------------
// TF32 tensor-core GEMM, cp.async double-buffered, A-frags via ldmatrix.
// C = A(MxK) @ B(KxN) (+bias). A,B already tf32-rounded.
// BM=128, BN=128, BK=32. 256 threads = 8 warps (2m x 4n), warp tile 64x32.
// ---------------------------------------------------------------------------
template<bool HAS_BIAS, bool ROUND_OUT>
__global__ __launch_bounds__(256, 2)
void gemm_tf32_kernel(const float* __restrict__ A, const float* __restrict__ B,
                      const float* __restrict__ bias, float* __restrict__ Cmat,
                      int Mx, int Nx, int Kx)
{
    constexpr int BM = 128, BN = 128, BK = 32;
    constexpr int ASTR = 36, BSTR = 132;
    constexpr int ASZ = BM * ASTR, BSZ = BK * BSTR;
    extern __shared__ float smem[];
    float* Asb[2] = { smem, smem + ASZ };
    float* Bsb[2] = { smem + 2 * ASZ, smem + 2 * ASZ + BSZ };

    const int tid  = threadIdx.x;
    const int lane = tid & 31;
    const int wid  = tid >> 5;
    const int wm   = wid >> 2;
    const int wn   = wid & 3;
    const int grp  = lane >> 2;
    const int qid  = lane & 3;
    const int bm = blockIdx.y * BM;
    const int bn = blockIdx.x * BN;

    // ldmatrix A-pattern lane coords: sub = lane>>3
    const int a_lrow = ((lane >> 3) & 1) * 8 + (lane & 7);  // row within 16
    const int a_lcol = (lane >> 4) * 4;                     // 0 or 4

    const int a_row = tid >> 3, a_k4 = (tid & 7) * 4;
    const int b_row = tid >> 5, b_n4 = (tid & 31) * 4;

    const float* Aptr = A + (size_t)(bm + a_row) * Kx + a_k4;
    const float* Bptr = B + (size_t)b_row * Nx + bn + b_n4;

    uint32_t sA[2], sB[2], uA[2];
    sA[0] = (uint32_t)__cvta_generic_to_shared(Asb[0] + a_row * ASTR + a_k4);
    sA[1] = (uint32_t)__cvta_generic_to_shared(Asb[1] + a_row * ASTR + a_k4);
    sB[0] = (uint32_t)__cvta_generic_to_shared(Bsb[0] + b_row * BSTR + b_n4);
    sB[1] = (uint32_t)__cvta_generic_to_shared(Bsb[1] + b_row * BSTR + b_n4);
    uA[0] = (uint32_t)__cvta_generic_to_shared(Asb[0]);
    uA[1] = (uint32_t)__cvta_generic_to_shared(Asb[1]);

    const int ntiles = Kx / BK;

    auto issue = [&](int kt, int buf) {
        const float* Ag = Aptr + kt * BK;
        const float* Bg = Bptr + (size_t)kt * BK * Nx;
        #pragma unroll
        for (int t = 0; t < 4; t++)
            cp_async16(sA[buf] + t * (32 * ASTR * 4), Ag + (size_t)(t * 32) * Kx);
        #pragma unroll
        for (int t = 0; t < 4; t++)
            cp_async16(sB[buf] + t * (8 * BSTR * 4), Bg + (size_t)(t * 8) * Nx);
        cp_commit();
    };

    float acc[4][4][4];
    #pragma unroll
    for (int i = 0; i < 4; i++)
        #pragma unroll
        for (int j = 0; j < 4; j++)
            #pragma unroll
            for (int c = 0; c < 4; c++) acc[i][j][c] = 0.f;

    issue(0, 0);

    for (int kt = 0; kt < ntiles; kt++) {
        cp_wait0();
        __syncthreads();
        if (kt + 1 < ntiles) issue(kt + 1, (kt + 1) & 1);

        const int buf = kt & 1;
        const float* Bs_ = Bsb[buf];
        const uint32_t uAb = uA[buf];
        #pragma unroll
        for (int s = 0; s < 4; s++) {
            const int k0 = s * 8;
            uint32_t afr[4][4];
            uint32_t bfr[4][2];
            #pragma unroll
            for (int mt = 0; mt < 4; mt++) {
                uint32_t addr = uAb + (uint32_t)(((wm * 64 + mt * 16 + a_lrow) * ASTR + k0 + a_lcol) * 4);
                ldsm_x4(afr[mt], addr);
            }
            #pragma unroll
            for (int nt = 0; nt < 4; nt++) {
                int cb = wn * 32 + nt * 8 + grp;
                bfr[nt][0] = __float_as_uint(Bs_[(k0 + qid    ) * BSTR + cb]);
                bfr[nt][1] = __float_as_uint(Bs_[(k0 + qid + 4) * BSTR + cb]);
            }
            #pragma unroll
            for (int mt = 0; mt < 4; mt++)
                #pragma unroll
                for (int nt = 0; nt < 4; nt++)
                    mma_tf32(acc[mt][nt], afr[mt], bfr[nt][0], bfr[nt][1]);
        }
    }

    #pragma unroll
    for (int mt = 0; mt < 4; mt++) {
        #pragma unroll
        for (int nt = 0; nt < 4; nt++) {
            int row = bm + wm * 64 + mt * 16 + grp;
            int col = bn + wn * 32 + nt * 8 + qid * 2;
            float2 v0 = make_float2(acc[mt][nt][0], acc[mt][nt][1]);
            float2 v1 = make_float2(acc[mt][nt][2], acc[mt][nt][3]);
            if (HAS_BIAS) {
                float2 bb = *(const float2*)&bias[col];
                v0.x += bb.x; v0.y += bb.y;
                v1.x += bb.x; v1.y += bb.y;
            }
            if (ROUND_OUT) {
                v0.x = to_tf32(v0.x); v0.y = to_tf32(v0.y);
                v1.x = to_tf32(v1.x); v1.y = to_tf32(v1.y);
            }
            *(float2*)&Cmat[(size_t)row * Nx + col]       = v0;
            *(float2*)&Cmat[(size_t)(row + 8) * Nx + col] = v1;
        }
    }
}

// ---------------------------------------------------------------------------
// MMA flash-attention (tf32, causal), all fragments via ldmatrix.
// CTA = 64 queries x (b,h); 4 warps, warp w owns rows [16w,16w+16).
// Q [q][d], K [j][d], Vt [d][j], P [r][j] -- every operand's smem layout
// matches the 8x4-b32 ldmatrix submatrix pattern; stride 68 -> LDSM rows
// cover all 32 banks (conflict-free).
// ---------------------------------------------------------------------------
__global__ __launch_bounds__(128)
void attn_mma_kernel(const float* __restrict__ qkv, float* __restrict__ y)
{
    constexpr int STR = 68;
    extern __shared__ float sm[];
    float* Qs = sm;                  // [64 q][68]  pre-scaled
    float* Ks = Qs + 64 * STR;       // [64 j][68]
    float* Vt = Ks + 64 * STR;       // [64 d][68]
    float* Ps = Vt + 64 * STR;       // [4 warps][16 r][68]

    const int tid  = threadIdx.x;
    const int lane = tid & 31;
    const int w    = tid >> 5;
    const int grp  = lane >> 2;
    const int qid  = lane & 3;
    const int qt   = (int)gridDim.x - 1 - (int)blockIdx.x;
    const int bh   = blockIdx.y;
    const int b    = bh >> 4;
    const int h    = bh & 15;
    const float scale = 0.125f;

    // ldmatrix lane coords
    const int a_lrow = ((lane >> 3) & 1) * 8 + (lane & 7);   // A-pattern row
    const int a_lcol = (lane >> 4) * 4;                      // A-pattern col
    const int b_lrow = (lane >> 4) * 8 + (lane & 7);         // B-pattern row (within 16-row pair)
    const int b_lcol = ((lane >> 3) & 1) * 4;                // B-pattern col

    const float* qbase = qkv + (size_t)(b * SEQ) * (3 * CH) + h * HD;
    const float* kbase = qbase + CH;
    const float* vbase = qbase + 2 * CH;

    float* Pw = Ps + w * 16 * STR;
    const uint32_t uQ  = (uint32_t)__cvta_generic_to_shared(Qs);
    const uint32_t uK  = (uint32_t)__cvta_generic_to_shared(Ks);
    const uint32_t uV  = (uint32_t)__cvta_generic_to_shared(Vt);
    const uint32_t uP  = (uint32_t)__cvta_generic_to_shared(Pw);

    // Load Q tile 64x64 (8 float4 per thread), scale (exact), [q][d]
    #pragma unroll
    for (int t = 0; t < 8; t++) {
        int f   = tid + t * 128;
        int row = f >> 4;
        int c4  = (f & 15) * 4;
        float4 v = *(const float4*)&qbase[(size_t)(qt * 64 + row) * (3 * CH) + c4];
        v.x *= scale; v.y *= scale; v.z *= scale; v.w *= scale;
        *(float4*)&Qs[row * STR + c4] = v;
    }

    float o[8][4];
    #pragma unroll
    for (int nt = 0; nt < 8; nt++)
        #pragma unroll
        for (int c = 0; c < 4; c++) o[nt][c] = 0.f;
    float m0 = -1e30f, m1 = -1e30f, l0 = 0.f, l1 = 0.f;

    const int row0 = 16 * w + grp;
    const int row1 = row0 + 8;

    for (int kt = 0; kt <= qt; kt++) {
        __syncthreads();
        #pragma unroll
        for (int t = 0; t < 8; t++) {
            int f   = tid + t * 128;
            int row = f >> 4;
            int c4  = (f & 15) * 4;
            float4 kv = *(const float4*)&kbase[(size_t)(kt * 64 + row) * (3 * CH) + c4];
            *(float4*)&Ks[row * STR + c4] = kv;
            float4 vv = *(const float4*)&vbase[(size_t)(kt * 64 + row) * (3 * CH) + c4];
            Vt[(c4 + 0) * STR + row] = vv.x;
            Vt[(c4 + 1) * STR + row] = vv.y;
            Vt[(c4 + 2) * STR + row] = vv.z;
            Vt[(c4 + 3) * STR + row] = vv.w;
        }
        __syncthreads();

        // ---- S = Q @ K^T  (1 Q-LDSM + 4 K-LDSM + 8 MMA per k8 step)
        float sfr[8][4];
        #pragma unroll
        for (int nt = 0; nt < 8; nt++)
            #pragma unroll
            for (int c = 0; c < 4; c++) sfr[nt][c] = 0.f;

        #pragma unroll
        for (int s = 0; s < 8; s++) {
            const int k0 = s * 8;
            uint32_t qf[4];
            ldsm_x4(qf, uQ + (uint32_t)(((16 * w + a_lrow) * STR + k0 + a_lcol) * 4));
            #pragma unroll
            for (int p = 0; p < 4; p++) {
                uint32_t kf[4];
                ldsm_x4(kf, uK + (uint32_t)(((p * 16 + b_lrow) * STR + k0 + b_lcol) * 4));
                mma_tf32(sfr[2 * p    ], qf, kf[0], kf[1]);
                mma_tf32(sfr[2 * p + 1], qf, kf[2], kf[3]);
            }
        }

        // ---- causal mask on diagonal tile
        if (kt == qt) {
            #pragma unroll
            for (int nt = 0; nt < 8; nt++) {
                int j0 = nt * 8 + qid * 2;
                if (j0     > row0) sfr[nt][0] = -1e30f;
                if (j0 + 1 > row0) sfr[nt][1] = -1e30f;
                if (j0     > row1) sfr[nt][2] = -1e30f;
                if (j0 + 1 > row1) sfr[nt][3] = -1e30f;
            }
        }

        // ---- online softmax
        float mx0 = -1e30f, mx1 = -1e30f;
        #pragma unroll
        for (int nt = 0; nt < 8; nt++) {
            mx0 = fmaxf(mx0, fmaxf(sfr[nt][0], sfr[nt][1]));
            mx1 = fmaxf(mx1, fmaxf(sfr[nt][2], sfr[nt][3]));
        }
        #pragma unroll
        for (int off = 1; off <= 2; off <<= 1) {
            mx0 = fmaxf(mx0, __shfl_xor_sync(0xffffffffu, mx0, off));
            mx1 = fmaxf(mx1, __shfl_xor_sync(0xffffffffu, mx1, off));
        }
        float mnew0 = fmaxf(m0, mx0), mnew1 = fmaxf(m1, mx1);
        float alpha0 = __expf(m0 - mnew0), alpha1 = __expf(m1 - mnew1);
        float sum0 = 0.f, sum1 = 0.f;
        #pragma unroll
        for (int nt = 0; nt < 8; nt++) {
            sfr[nt][0] = __expf(sfr[nt][0] - mnew0);
            sfr[nt][1] = __expf(sfr[nt][1] - mnew0);
            sfr[nt][2] = __expf(sfr[nt][2] - mnew1);
            sfr[nt][3] = __expf(sfr[nt][3] - mnew1);
            sum0 += sfr[nt][0] + sfr[nt][1];
            sum1 += sfr[nt][2] + sfr[nt][3];
        }
        #pragma unroll
        for (int off = 1; off <= 2; off <<= 1) {
            sum0 += __shfl_xor_sync(0xffffffffu, sum0, off);
            sum1 += __shfl_xor_sync(0xffffffffu, sum1, off);
        }
        l0 = l0 * alpha0 + sum0;  m0 = mnew0;
        l1 = l1 * alpha1 + sum1;  m1 = mnew1;

        // ---- write P (tf32) to per-warp smem; rescale O
        #pragma unroll
        for (int nt = 0; nt < 8; nt++) {
            int cc = nt * 8 + qid * 2;
            float2 p0 = make_float2(to_tf32(sfr[nt][0]), to_tf32(sfr[nt][1]));
            float2 p1 = make_float2(to_tf32(sfr[nt][2]), to_tf32(sfr[nt][3]));
            *(float2*)&Pw[(grp    ) * STR + cc] = p0;
            *(float2*)&Pw[(grp + 8) * STR + cc] = p1;
            o[nt][0] *= alpha0; o[nt][1] *= alpha0;
            o[nt][2] *= alpha1; o[nt][3] *= alpha1;
        }
        __syncwarp();

        // ---- O += P @ V  (1 P-LDSM + 4 V-LDSM + 8 MMA per k8 step)
        #pragma unroll
        for (int s = 0; s < 8; s++) {
            const int k0 = s * 8;
            uint32_t pf[4];
            ldsm_x4(pf, uP + (uint32_t)((a_lrow * STR + k0 + a_lcol) * 4));
            #pragma unroll
            for (int p = 0; p < 4; p++) {
                uint32_t vf[4];
                ldsm_x4(vf, uV + (uint32_t)(((p * 16 + b_lrow) * STR + k0 + b_lcol) * 4));
                mma_tf32(o[2 * p    ], pf, vf[0], vf[1]);
                mma_tf32(o[2 * p + 1], pf, vf[2], vf[3]);
            }
        }
        __syncwarp();
    }

    // ---- normalize + write y (tf32-rounded, feeds tf32 GEMM2)
    float inv0 = 1.0f / l0, inv1 = 1.0f / l1;
    int gr0 = qt * 64 + row0, gr1 = qt * 64 + row1;
    #pragma unroll
    for (int nt = 0; nt < 8; nt++) {
        int d = nt * 8 + qid * 2;
        float2 v0 = make_float2(to_tf32(o[nt][0] * inv0), to_tf32(o[nt][1] * inv0));
        float2 v1 = make_float2(to_tf32(o[nt][2] * inv1), to_tf32(o[nt][3] * inv1));
        *(float2*)&y[(size_t)(b * SEQ + gr0) * CH + h * HD + d] = v0;
        *(float2*)&y[(size_t)(b * SEQ + gr1) * CH + h * HD + d] = v1;
    }
}

// ---------------------------------------------------------------------------

static constexpr int GEMM_SMEM = (2 * 128 * 36 + 2 * 32 * 132) * 4;   // 70656 B
static constexpr int ATTN_SMEM = (64 * 68 * 3 + 4 * 16 * 68) * 4;     // 69632 B

extern "C" void kernel_launch(void* const* d_in, const int* in_sizes, int n_in,
                              void* d_out, int out_size)
{
    (void)in_sizes; (void)n_in; (void)out_size;
    const float* x     = (const float*)d_in[0];
    const float* w_qkv = (const float*)d_in[1];
    const float* w_out = (const float*)d_in[2];
    const float* b_out = (const float*)d_in[3];
    float* out = (float*)d_out;

    float *qkv, *y, *xc, *wq, *wo;
    cudaGetSymbolAddress((void**)&qkv, g_qkv);
    cudaGetSymbolAddress((void**)&y,   g_y);
    cudaGetSymbolAddress((void**)&xc,  g_x);
    cudaGetSymbolAddress((void**)&wq,  g_wq);
    cudaGetSymbolAddress((void**)&wo,  g_wo);

    cudaFuncSetAttribute(gemm_tf32_kernel<false, true>,
                         cudaFuncAttributeMaxDynamicSharedMemorySize, GEMM_SMEM);
    cudaFuncSetAttribute(gemm_tf32_kernel<true, false>,
                         cudaFuncAttributeMaxDynamicSharedMemorySize, GEMM_SMEM);
    cudaFuncSetAttribute(attn_mma_kernel,
                         cudaFuncAttributeMaxDynamicSharedMemorySize, ATTN_SMEM);

    // 0) pre-round operands to tf32 (rna), once
    cvt_tf32_kernel<<<(MROWS * CH / 4 + 255) / 256, 256>>>(
        (const float4*)x, (float4*)xc, MROWS * CH / 4);
    cvt_tf32_kernel<<<(CH * 3 * CH / 4 + 255) / 256, 256>>>(
        (const float4*)w_qkv, (float4*)wq, CH * 3 * CH / 4);
    cvt_tf32_kernel<<<(CH * CH / 4 + 255) / 256, 256>>>(
        (const float4*)w_out, (float4*)wo, CH * CH / 4);

    // 1) qkv = x @ w_qkv  (tf32 TC, cp.async + ldmatrix), output tf32-rounded
    gemm_tf32_kernel<false, true><<<dim3(3 * CH / 128, MROWS / 128), 256, GEMM_SMEM>>>(
        xc, wq, nullptr, qkv, MROWS, 3 * CH, CH);

    // 2) causal flash attention -> y (tf32 TC, ldmatrix), output tf32-rounded
    attn_mma_kernel<<<dim3(SEQ / 64, BATCH * NH), 128, ATTN_SMEM>>>(qkv, y);

    // 3) out = y @ w_out + b_out  (tf32 TC, cp.async + ldmatrix), fp32 output
    gemm_tf32_kernel<true, false><<<dim3(CH / 128, MROWS / 128), 256, GEMM_SMEM>>>(
        y, wo, b_out, out, MROWS, CH, CH);
}

// round 10
// speedup vs baseline: 2.7223x; 1.0332x over previous
#include <cuda_runtime.h>
#include <cstdint>

#define BATCH 2
#define SEQ   2048
#define CH    1024
#define NH    16
#define HD    64
#define MROWS (BATCH*SEQ)   /* 4096 */

// Scratch (allocation-free rule: __device__ globals)
__device__ float g_qkv[MROWS * 3 * CH];   // tf32-rounded qkv
__device__ float g_y  [MROWS * CH];       // tf32-rounded attn out
__device__ float g_x  [MROWS * CH];       // tf32-rounded x
__device__ float g_wq [CH * 3 * CH];      // tf32-rounded w_qkv
__device__ float g_wo [CH * CH];          // tf32-rounded w_out

// ---------------------------------------------------------------------------
// TF32 / MMA / cp.async / ldmatrix helpers
// ---------------------------------------------------------------------------
__device__ __forceinline__ uint32_t to_tf32_bits(float x) {
    uint32_t y;
    asm("cvt.rna.tf32.f32 %0, %1;" : "=r"(y) : "f"(x));
    return y;
}
__device__ __forceinline__ float to_tf32(float x) {
    return __uint_as_float(to_tf32_bits(x));
}

__device__ __forceinline__ void mma_tf32(float c[4], const uint32_t a[4], const uint32_t b0, const uint32_t b1) {
    asm volatile(
        "mma.sync.aligned.m16n8k8.row.col.f32.tf32.tf32.f32 "
        "{%0,%1,%2,%3}, {%4,%5,%6,%7}, {%8,%9}, {%0,%1,%2,%3};"
        : "+f"(c[0]), "+f"(c[1]), "+f"(c[2]), "+f"(c[3])
        : "r"(a[0]), "r"(a[1]), "r"(a[2]), "r"(a[3]),
          "r"(b0), "r"(b1));
}

__device__ __forceinline__ void ldsm_x4(uint32_t r[4], uint32_t saddr) {
    asm volatile("ldmatrix.sync.aligned.m8n8.x4.shared.b16 {%0,%1,%2,%3}, [%4];"
        : "=r"(r[0]), "=r"(r[1]), "=r"(r[2]), "=r"(r[3]) : "r"(saddr));
}

__device__ __forceinline__ void cp_async16(uint32_t saddr, const void* gptr) {
    asm volatile("cp.async.cg.shared.global [%0], [%1], 16;" :: "r"(saddr), "l"(gptr));
}
__device__ __forceinline__ void cp_commit() {
    asm volatile("cp.async.commit_group;");
}
__device__ __forceinline__ void cp_wait0() {
    asm volatile("cp.async.wait_group 0;");
}

// ---------------------------------------------------------------------------
// Elementwise tf32 rounding (float4 granularity)
// ---------------------------------------------------------------------------
__global__ void cvt_tf32_kernel(const float4* __restrict__ in, float4* __restrict__ out, int n4)
{
    int i = blockIdx.x * blockDim.x + threadIdx.x;
    if (i < n4) {
        float4 v = in[i];
        v.x = to_tf32(v.x); v.y = to_tf32(v.y);
        v.z = to_tf32(v.z); v.w = to_tf32(v.w);
        out[i] = v;
    }
}

// ---------------------------------------------------------------------------
// TF32 tensor-core GEMM, cp.async double-buffered, A-frags via ldmatrix.
// (unchanged from R9 passing kernel)
// ---------------------------------------------------------------------------
template<bool HAS_BIAS, bool ROUND_OUT>
__global__ __launch_bounds__(256, 2)
void gemm_tf32_kernel(const float* __restrict__ A, const float* __restrict__ B,
                      const float* __restrict__ bias, float* __restrict__ Cmat,
                      int Mx, int Nx, int Kx)
{
    constexpr int BM = 128, BN = 128, BK = 32;
    constexpr int ASTR = 36, BSTR = 132;
    constexpr int ASZ = BM * ASTR, BSZ = BK * BSTR;
    extern __shared__ float smem[];
    float* Asb[2] = { smem, smem + ASZ };
    float* Bsb[2] = { smem + 2 * ASZ, smem + 2 * ASZ + BSZ };

    const int tid  = threadIdx.x;
    const int lane = tid & 31;
    const int wid  = tid >> 5;
    const int wm   = wid >> 2;
    const int wn   = wid & 3;
    const int grp  = lane >> 2;
    const int qid  = lane & 3;
    const int bm = blockIdx.y * BM;
    const int bn = blockIdx.x * BN;

    const int a_lrow = ((lane >> 3) & 1) * 8 + (lane & 7);
    const int a_lcol = (lane >> 4) * 4;

    const int a_row = tid >> 3, a_k4 = (tid & 7) * 4;
    const int b_row = tid >> 5, b_n4 = (tid & 31) * 4;

    const float* Aptr = A + (size_t)(bm + a_row) * Kx + a_k4;
    const float* Bptr = B + (size_t)b_row * Nx + bn + b_n4;

    uint32_t sA[2], sB[2], uA[2];
    sA[0] = (uint32_t)__cvta_generic_to_shared(Asb[0] + a_row * ASTR + a_k4);
    sA[1] = (uint32_t)__cvta_generic_to_shared(Asb[1] + a_row * ASTR + a_k4);
    sB[0] = (uint32_t)__cvta_generic_to_shared(Bsb[0] + b_row * BSTR + b_n4);
    sB[1] = (uint32_t)__cvta_generic_to_shared(Bsb[1] + b_row * BSTR + b_n4);
    uA[0] = (uint32_t)__cvta_generic_to_shared(Asb[0]);
    uA[1] = (uint32_t)__cvta_generic_to_shared(Asb[1]);

    const int ntiles = Kx / BK;

    auto issue = [&](int kt, int buf) {
        const float* Ag = Aptr + kt * BK;
        const float* Bg = Bptr + (size_t)kt * BK * Nx;
        #pragma unroll
        for (int t = 0; t < 4; t++)
            cp_async16(sA[buf] + t * (32 * ASTR * 4), Ag + (size_t)(t * 32) * Kx);
        #pragma unroll
        for (int t = 0; t < 4; t++)
            cp_async16(sB[buf] + t * (8 * BSTR * 4), Bg + (size_t)(t * 8) * Nx);
        cp_commit();
    };

    float acc[4][4][4];
    #pragma unroll
    for (int i = 0; i < 4; i++)
        #pragma unroll
        for (int j = 0; j < 4; j++)
            #pragma unroll
            for (int c = 0; c < 4; c++) acc[i][j][c] = 0.f;

    issue(0, 0);

    for (int kt = 0; kt < ntiles; kt++) {
        cp_wait0();
        __syncthreads();
        if (kt + 1 < ntiles) issue(kt + 1, (kt + 1) & 1);

        const int buf = kt & 1;
        const float* Bs_ = Bsb[buf];
        const uint32_t uAb = uA[buf];
        #pragma unroll
        for (int s = 0; s < 4; s++) {
            const int k0 = s * 8;
            uint32_t afr[4][4];
            uint32_t bfr[4][2];
            #pragma unroll
            for (int mt = 0; mt < 4; mt++) {
                uint32_t addr = uAb + (uint32_t)(((wm * 64 + mt * 16 + a_lrow) * ASTR + k0 + a_lcol) * 4);
                ldsm_x4(afr[mt], addr);
            }
            #pragma unroll
            for (int nt = 0; nt < 4; nt++) {
                int cb = wn * 32 + nt * 8 + grp;
                bfr[nt][0] = __float_as_uint(Bs_[(k0 + qid    ) * BSTR + cb]);
                bfr[nt][1] = __float_as_uint(Bs_[(k0 + qid + 4) * BSTR + cb]);
            }
            #pragma unroll
            for (int mt = 0; mt < 4; mt++)
                #pragma unroll
                for (int nt = 0; nt < 4; nt++)
                    mma_tf32(acc[mt][nt], afr[mt], bfr[nt][0], bfr[nt][1]);
        }
    }

    #pragma unroll
    for (int mt = 0; mt < 4; mt++) {
        #pragma unroll
        for (int nt = 0; nt < 4; nt++) {
            int row = bm + wm * 64 + mt * 16 + grp;
            int col = bn + wn * 32 + nt * 8 + qid * 2;
            float2 v0 = make_float2(acc[mt][nt][0], acc[mt][nt][1]);
            float2 v1 = make_float2(acc[mt][nt][2], acc[mt][nt][3]);
            if (HAS_BIAS) {
                float2 bb = *(const float2*)&bias[col];
                v0.x += bb.x; v0.y += bb.y;
                v1.x += bb.x; v1.y += bb.y;
            }
            if (ROUND_OUT) {
                v0.x = to_tf32(v0.x); v0.y = to_tf32(v0.y);
                v1.x = to_tf32(v1.x); v1.y = to_tf32(v1.y);
            }
            *(float2*)&Cmat[(size_t)row * Nx + col]       = v0;
            *(float2*)&Cmat[(size_t)(row + 8) * Nx + col] = v1;
        }
    }
}

// ---------------------------------------------------------------------------
// MMA flash-attention (tf32, causal), 128-query tiles, 8 warps,
// cp.async double-buffered K/V.
// Warp w owns rows [16w, 16w+16) of the 128-row Q tile. K-tiles of 64.
// Q [q][d] (LDSM A-frags), K [j][d] (LDSM B-frags), V [j][d] (scalar LDS
// B-frags: thread(grp,qid) reads V[k0+qid][8nt+grp]), P via per-warp smem
// (LDSM A-frags). Numerics bit-identical to the 64-tile version.
// ---------------------------------------------------------------------------
__global__ __launch_bounds__(256)
void attn_mma_kernel(const float* __restrict__ qkv, float* __restrict__ y)
{
    constexpr int STR = 68;
    extern __shared__ float sm[];
    float* Qs  = sm;                    // [128 q][68]  pre-scaled
    float* Ksb = Qs  + 128 * STR;       // [2][64 j][68]
    float* Vsb = Ksb + 2 * 64 * STR;    // [2][64 j][68]
    float* Ps  = Vsb + 2 * 64 * STR;    // [8 warps][16 r][68]

    const int tid  = threadIdx.x;
    const int lane = tid & 31;
    const int w    = tid >> 5;          // 0..7
    const int grp  = lane >> 2;
    const int qid  = lane & 3;
    const int qt   = (int)gridDim.x - 1 - (int)blockIdx.x;  // longest first
    const int bh   = blockIdx.y;
    const int b    = bh >> 4;
    const int h    = bh & 15;
    const float scale = 0.125f;

    const int a_lrow = ((lane >> 3) & 1) * 8 + (lane & 7);   // A-pattern row
    const int a_lcol = (lane >> 4) * 4;                      // A-pattern col
    const int b_lrow = (lane >> 4) * 8 + (lane & 7);         // B-pattern row
    const int b_lcol = ((lane >> 3) & 1) * 4;                // B-pattern col

    const float* qbase = qkv + (size_t)(b * SEQ) * (3 * CH) + h * HD;
    const float* kbase = qbase + CH;
    const float* vbase = qbase + 2 * CH;

    float* Pw = Ps + w * 16 * STR;
    const uint32_t uQ  = (uint32_t)__cvta_generic_to_shared(Qs);
    const uint32_t uKs = (uint32_t)__cvta_generic_to_shared(Ksb);
    const uint32_t uVs = (uint32_t)__cvta_generic_to_shared(Vsb);
    const uint32_t uP  = (uint32_t)__cvta_generic_to_shared(Pw);

    // Load Q tile 128x64 (8 float4 per thread), scale (exact), [q][d]
    #pragma unroll
    for (int t = 0; t < 8; t++) {
        int f   = tid + t * 256;        // 0..2047
        int row = f >> 4;
        int c4  = (f & 15) * 4;
        float4 v = *(const float4*)&qbase[(size_t)(qt * 128 + row) * (3 * CH) + c4];
        v.x *= scale; v.y *= scale; v.z *= scale; v.w *= scale;
        *(float4*)&Qs[row * STR + c4] = v;
    }

    // cp.async K/V tile issue (64 rows x 64 floats each; 4 float4/thread/tensor)
    const int ld_row = tid >> 4;            // 0..15 (advance by 16 rows x 4 iters)
    const int ld_c4  = (tid & 15) * 4;
    auto issueKV = [&](int kt, int buf) {
        const float* Kg = kbase + (size_t)(kt * 64 + ld_row) * (3 * CH) + ld_c4;
        const float* Vg = vbase + (size_t)(kt * 64 + ld_row) * (3 * CH) + ld_c4;
        uint32_t dK = uKs + (uint32_t)((buf * 64 + ld_row) * STR + ld_c4) * 4;
        uint32_t dV = uVs + (uint32_t)((buf * 64 + ld_row) * STR + ld_c4) * 4;
        #pragma unroll
        for (int t = 0; t < 4; t++) {
            cp_async16(dK + t * (16 * STR * 4), Kg + (size_t)(t * 16) * (3 * CH));
            cp_async16(dV + t * (16 * STR * 4), Vg + (size_t)(t * 16) * (3 * CH));
        }
        cp_commit();
    };

    float o[8][4];
    #pragma unroll
    for (int nt = 0; nt < 8; nt++)
        #pragma unroll
        for (int c = 0; c < 4; c++) o[nt][c] = 0.f;
    float m0 = -1e30f, m1 = -1e30f, l0 = 0.f, l1 = 0.f;

    const int row0 = 16 * w + grp;          // local rows
    const int row1 = row0 + 8;
    const int gi0  = qt * 128 + row0;       // global rows (for mask)
    const int gi1  = gi0 + 8;

    const int last = 2 * qt + 1;
    issueKV(0, 0);

    for (int kt = 0; kt <= last; kt++) {
        cp_wait0();
        __syncthreads();                 // tile kt visible; prev compute done
        if (kt < last) issueKV(kt + 1, (kt + 1) & 1);

        const int buf = kt & 1;
        const uint32_t uKb = uKs + (uint32_t)(buf * 64 * STR) * 4;
        const float*   Vb  = Vsb + buf * 64 * STR;

        // ---- S = Q @ K^T  (1 Q-LDSM + 4 K-LDSM + 8 MMA per k8 step)
        float sfr[8][4];
        #pragma unroll
        for (int nt = 0; nt < 8; nt++)
            #pragma unroll
            for (int c = 0; c < 4; c++) sfr[nt][c] = 0.f;

        #pragma unroll
        for (int s = 0; s < 8; s++) {
            const int k0 = s * 8;
            uint32_t qf[4];
            ldsm_x4(qf, uQ + (uint32_t)(((16 * w + a_lrow) * STR + k0 + a_lcol) * 4));
            #pragma unroll
            for (int p = 0; p < 4; p++) {
                uint32_t kf[4];
                ldsm_x4(kf, uKb + (uint32_t)(((p * 16 + b_lrow) * STR + k0 + b_lcol) * 4));
                mma_tf32(sfr[2 * p    ], qf, kf[0], kf[1]);
                mma_tf32(sfr[2 * p + 1], qf, kf[2], kf[3]);
            }
        }

        // ---- causal mask (global indices; tiles kt >= 2*qt may intersect diag)
        if (kt >= 2 * qt) {
            #pragma unroll
            for (int nt = 0; nt < 8; nt++) {
                int j0 = kt * 64 + nt * 8 + qid * 2;
                if (j0     > gi0) sfr[nt][0] = -1e30f;
                if (j0 + 1 > gi0) sfr[nt][1] = -1e30f;
                if (j0     > gi1) sfr[nt][2] = -1e30f;
                if (j0 + 1 > gi1) sfr[nt][3] = -1e30f;
            }
        }

        // ---- online softmax
        float mx0 = -1e30f, mx1 = -1e30f;
        #pragma unroll
        for (int nt = 0; nt < 8; nt++) {
            mx0 = fmaxf(mx0, fmaxf(sfr[nt][0], sfr[nt][1]));
            mx1 = fmaxf(mx1, fmaxf(sfr[nt][2], sfr[nt][3]));
        }
        #pragma unroll
        for (int off = 1; off <= 2; off <<= 1) {
            mx0 = fmaxf(mx0, __shfl_xor_sync(0xffffffffu, mx0, off));
            mx1 = fmaxf(mx1, __shfl_xor_sync(0xffffffffu, mx1, off));
        }
        float mnew0 = fmaxf(m0, mx0), mnew1 = fmaxf(m1, mx1);
        float alpha0 = __expf(m0 - mnew0), alpha1 = __expf(m1 - mnew1);
        float sum0 = 0.f, sum1 = 0.f;
        #pragma unroll
        for (int nt = 0; nt < 8; nt++) {
            sfr[nt][0] = __expf(sfr[nt][0] - mnew0);
            sfr[nt][1] = __expf(sfr[nt][1] - mnew0);
            sfr[nt][2] = __expf(sfr[nt][2] - mnew1);
            sfr[nt][3] = __expf(sfr[nt][3] - mnew1);
            sum0 += sfr[nt][0] + sfr[nt][1];
            sum1 += sfr[nt][2] + sfr[nt][3];
        }
        #pragma unroll
        for (int off = 1; off <= 2; off <<= 1) {
            sum0 += __shfl_xor_sync(0xffffffffu, sum0, off);
            sum1 += __shfl_xor_sync(0xffffffffu, sum1, off);
        }
        l0 = l0 * alpha0 + sum0;  m0 = mnew0;
        l1 = l1 * alpha1 + sum1;  m1 = mnew1;

        // ---- write P (tf32) to per-warp smem; rescale O
        #pragma unroll
        for (int nt = 0; nt < 8; nt++) {
            int cc = nt * 8 + qid * 2;
            float2 p0 = make_float2(to_tf32(sfr[nt][0]), to_tf32(sfr[nt][1]));
            float2 p1 = make_float2(to_tf32(sfr[nt][2]), to_tf32(sfr[nt][3]));
            *(float2*)&Pw[(grp    ) * STR + cc] = p0;
            *(float2*)&Pw[(grp + 8) * STR + cc] = p1;
            o[nt][0] *= alpha0; o[nt][1] *= alpha0;
            o[nt][2] *= alpha1; o[nt][3] *= alpha1;
        }
        __syncwarp();

        // ---- O += P @ V  (1 P-LDSM + scalar V B-frags + 8 MMA per k8 step)
        #pragma unroll
        for (int s = 0; s < 8; s++) {
            const int k0 = s * 8;
            uint32_t pf[4];
            ldsm_x4(pf, uP + (uint32_t)((a_lrow * STR + k0 + a_lcol) * 4));
            const float* v0r = Vb + (k0 + qid    ) * STR + grp;
            const float* v1r = Vb + (k0 + qid + 4) * STR + grp;
            #pragma unroll
            for (int nt = 0; nt < 8; nt++) {
                uint32_t bf0 = __float_as_uint(v0r[nt * 8]);
                uint32_t bf1 = __float_as_uint(v1r[nt * 8]);
                mma_tf32(o[nt], pf, bf0, bf1);
            }
        }
        __syncwarp();
    }

    // ---- normalize + write y (tf32-rounded, feeds tf32 GEMM2)
    float inv0 = 1.0f / l0, inv1 = 1.0f / l1;
    #pragma unroll
    for (int nt = 0; nt < 8; nt++) {
        int d = nt * 8 + qid * 2;
        float2 v0 = make_float2(to_tf32(o[nt][0] * inv0), to_tf32(o[nt][1] * inv0));
        float2 v1 = make_float2(to_tf32(o[nt][2] * inv1), to_tf32(o[nt][3] * inv1));
        *(float2*)&y[(size_t)(b * SEQ + gi0) * CH + h * HD + d] = v0;
        *(float2*)&y[(size_t)(b * SEQ + gi1) * CH + h * HD + d] = v1;
    }
}

// ---------------------------------------------------------------------------

static constexpr int GEMM_SMEM = (2 * 128 * 36 + 2 * 32 * 132) * 4;   // 70656 B
static constexpr int ATTN_SMEM = (128 + 2 * 64 + 2 * 64 + 8 * 16) * 68 * 4;  // 139264 B

extern "C" void kernel_launch(void* const* d_in, const int* in_sizes, int n_in,
                              void* d_out, int out_size)
{
    (void)in_sizes; (void)n_in; (void)out_size;
    const float* x     = (const float*)d_in[0];
    const float* w_qkv = (const float*)d_in[1];
    const float* w_out = (const float*)d_in[2];
    const float* b_out = (const float*)d_in[3];
    float* out = (float*)d_out;

    float *qkv, *y, *xc, *wq, *wo;
    cudaGetSymbolAddress((void**)&qkv, g_qkv);
    cudaGetSymbolAddress((void**)&y,   g_y);
    cudaGetSymbolAddress((void**)&xc,  g_x);
    cudaGetSymbolAddress((void**)&wq,  g_wq);
    cudaGetSymbolAddress((void**)&wo,  g_wo);

    cudaFuncSetAttribute(gemm_tf32_kernel<false, true>,
                         cudaFuncAttributeMaxDynamicSharedMemorySize, GEMM_SMEM);
    cudaFuncSetAttribute(gemm_tf32_kernel<true, false>,
                         cudaFuncAttributeMaxDynamicSharedMemorySize, GEMM_SMEM);
    cudaFuncSetAttribute(attn_mma_kernel,
                         cudaFuncAttributeMaxDynamicSharedMemorySize, ATTN_SMEM);

    // 0) pre-round operands to tf32 (rna), once
    cvt_tf32_kernel<<<(MROWS * CH / 4 + 255) / 256, 256>>>(
        (const float4*)x, (float4*)xc, MROWS * CH / 4);
    cvt_tf32_kernel<<<(CH * 3 * CH / 4 + 255) / 256, 256>>>(
        (const float4*)w_qkv, (float4*)wq, CH * 3 * CH / 4);
    cvt_tf32_kernel<<<(CH * CH / 4 + 255) / 256, 256>>>(
        (const float4*)w_out, (float4*)wo, CH * CH / 4);

    // 1) qkv = x @ w_qkv  (tf32 TC, cp.async + ldmatrix), output tf32-rounded
    gemm_tf32_kernel<false, true><<<dim3(3 * CH / 128, MROWS / 128), 256, GEMM_SMEM>>>(
        xc, wq, nullptr, qkv, MROWS, 3 * CH, CH);

    // 2) causal flash attention -> y (tf32 TC, 128-q tiles, cp.async K/V)
    attn_mma_kernel<<<dim3(SEQ / 128, BATCH * NH), 256, ATTN_SMEM>>>(qkv, y);

    // 3) out = y @ w_out + b_out  (tf32 TC, cp.async + ldmatrix), fp32 output
    gemm_tf32_kernel<true, false><<<dim3(CH / 128, MROWS / 128), 256, GEMM_SMEM>>>(
        y, wo, b_out, out, MROWS, CH, CH);
}

// round 12
// speedup vs baseline: 2.7302x; 1.0029x over previous
#include <cuda_runtime.h>
#include <cstdint>

#define BATCH 2
#define SEQ   2048
#define CH    1024
#define NH    16
#define HD    64
#define MROWS (BATCH*SEQ)   /* 4096 */

// Scratch (allocation-free rule: __device__ globals)
__device__ float g_qkv[MROWS * 3 * CH];   // tf32-rounded qkv
__device__ float g_y  [MROWS * CH];       // tf32-rounded attn out
__device__ float g_x  [MROWS * CH];       // tf32-rounded x
__device__ float g_wq [CH * 3 * CH];      // tf32-rounded w_qkv
__device__ float g_wo [CH * CH];          // tf32-rounded w_out

// ---------------------------------------------------------------------------
// TF32 / MMA / cp.async / ldmatrix helpers
// ---------------------------------------------------------------------------
__device__ __forceinline__ uint32_t to_tf32_bits(float x) {
    uint32_t y;
    asm("cvt.rna.tf32.f32 %0, %1;" : "=r"(y) : "f"(x));
    return y;
}
__device__ __forceinline__ float to_tf32(float x) {
    return __uint_as_float(to_tf32_bits(x));
}

__device__ __forceinline__ void mma_tf32(float c[4], const uint32_t a[4], const uint32_t b0, const uint32_t b1) {
    asm volatile(
        "mma.sync.aligned.m16n8k8.row.col.f32.tf32.tf32.f32 "
        "{%0,%1,%2,%3}, {%4,%5,%6,%7}, {%8,%9}, {%0,%1,%2,%3};"
        : "+f"(c[0]), "+f"(c[1]), "+f"(c[2]), "+f"(c[3])
        : "r"(a[0]), "r"(a[1]), "r"(a[2]), "r"(a[3]),
          "r"(b0), "r"(b1));
}

__device__ __forceinline__ void ldsm_x4(uint32_t r[4], uint32_t saddr) {
    asm volatile("ldmatrix.sync.aligned.m8n8.x4.shared.b16 {%0,%1,%2,%3}, [%4];"
        : "=r"(r[0]), "=r"(r[1]), "=r"(r[2]), "=r"(r[3]) : "r"(saddr));
}

__device__ __forceinline__ void cp_async16(uint32_t saddr, const void* gptr) {
    asm volatile("cp.async.cg.shared.global [%0], [%1], 16;" :: "r"(saddr), "l"(gptr));
}
__device__ __forceinline__ void cp_commit() { asm volatile("cp.async.commit_group;"); }
__device__ __forceinline__ void cp_wait0()  { asm volatile("cp.async.wait_group 0;"); }
__device__ __forceinline__ void cp_wait1()  { asm volatile("cp.async.wait_group 1;"); }

// ---------------------------------------------------------------------------
// Elementwise tf32 rounding (float4 granularity)
// ---------------------------------------------------------------------------
__global__ void cvt_tf32_kernel(const float4* __restrict__ in, float4* __restrict__ out, int n4)
{
    int i = blockIdx.x * blockDim.x + threadIdx.x;
    if (i < n4) {
        float4 v = in[i];
        v.x = to_tf32(v.x); v.y = to_tf32(v.y);
        v.z = to_tf32(v.z); v.w = to_tf32(v.w);
        out[i] = v;
    }
}

// ---------------------------------------------------------------------------
// TF32 tensor-core GEMM, cp.async double-buffered, A-frags via ldmatrix.
// (identical to R10 passing kernel)
// ---------------------------------------------------------------------------
template<bool HAS_BIAS, bool ROUND_OUT>
__global__ __launch_bounds__(256, 2)
void gemm_tf32_kernel(const float* __restrict__ A, const float* __restrict__ B,
                      const float* __restrict__ bias, float* __restrict__ Cmat,
                      int Mx, int Nx, int Kx)
{
    constexpr int BM = 128, BN = 128, BK = 32;
    constexpr int ASTR = 36, BSTR = 132;
    constexpr int ASZ = BM * ASTR, BSZ = BK * BSTR;
    extern __shared__ float smem[];
    float* Asb[2] = { smem, smem + ASZ };
    float* Bsb[2] = { smem + 2 * ASZ, smem + 2 * ASZ + BSZ };

    const int tid  = threadIdx.x;
    const int lane = tid & 31;
    const int wid  = tid >> 5;
    const int wm   = wid >> 2;
    const int wn   = wid & 3;
    const int grp  = lane >> 2;
    const int qid  = lane & 3;
    const int bm = blockIdx.y * BM;
    const int bn = blockIdx.x * BN;

    const int a_lrow = ((lane >> 3) & 1) * 8 + (lane & 7);
    const int a_lcol = (lane >> 4) * 4;

    const int a_row = tid >> 3, a_k4 = (tid & 7) * 4;
    const int b_row = tid >> 5, b_n4 = (tid & 31) * 4;

    const float* Aptr = A + (size_t)(bm + a_row) * Kx + a_k4;
    const float* Bptr = B + (size_t)b_row * Nx + bn + b_n4;

    uint32_t sA[2], sB[2], uA[2];
    sA[0] = (uint32_t)__cvta_generic_to_shared(Asb[0] + a_row * ASTR + a_k4);
    sA[1] = (uint32_t)__cvta_generic_to_shared(Asb[1] + a_row * ASTR + a_k4);
    sB[0] = (uint32_t)__cvta_generic_to_shared(Bsb[0] + b_row * BSTR + b_n4);
    sB[1] = (uint32_t)__cvta_generic_to_shared(Bsb[1] + b_row * BSTR + b_n4);
    uA[0] = (uint32_t)__cvta_generic_to_shared(Asb[0]);
    uA[1] = (uint32_t)__cvta_generic_to_shared(Asb[1]);

    const int ntiles = Kx / BK;

    auto issue = [&](int kt, int buf) {
        const float* Ag = Aptr + kt * BK;
        const float* Bg = Bptr + (size_t)kt * BK * Nx;
        #pragma unroll
        for (int t = 0; t < 4; t++)
            cp_async16(sA[buf] + t * (32 * ASTR * 4), Ag + (size_t)(t * 32) * Kx);
        #pragma unroll
        for (int t = 0; t < 4; t++)
            cp_async16(sB[buf] + t * (8 * BSTR * 4), Bg + (size_t)(t * 8) * Nx);
        cp_commit();
    };

    float acc[4][4][4];
    #pragma unroll
    for (int i = 0; i < 4; i++)
        #pragma unroll
        for (int j = 0; j < 4; j++)
            #pragma unroll
            for (int c = 0; c < 4; c++) acc[i][j][c] = 0.f;

    issue(0, 0);

    for (int kt = 0; kt < ntiles; kt++) {
        cp_wait0();
        __syncthreads();
        if (kt + 1 < ntiles) issue(kt + 1, (kt + 1) & 1);

        const int buf = kt & 1;
        const float* Bs_ = Bsb[buf];
        const uint32_t uAb = uA[buf];
        #pragma unroll
        for (int s = 0; s < 4; s++) {
            const int k0 = s * 8;
            uint32_t afr[4][4];
            uint32_t bfr[4][2];
            #pragma unroll
            for (int mt = 0; mt < 4; mt++) {
                uint32_t addr = uAb + (uint32_t)(((wm * 64 + mt * 16 + a_lrow) * ASTR + k0 + a_lcol) * 4);
                ldsm_x4(afr[mt], addr);
            }
            #pragma unroll
            for (int nt = 0; nt < 4; nt++) {
                int cb = wn * 32 + nt * 8 + grp;
                bfr[nt][0] = __float_as_uint(Bs_[(k0 + qid    ) * BSTR + cb]);
                bfr[nt][1] = __float_as_uint(Bs_[(k0 + qid + 4) * BSTR + cb]);
            }
            #pragma unroll
            for (int mt = 0; mt < 4; mt++)
                #pragma unroll
                for (int nt = 0; nt < 4; nt++)
                    mma_tf32(acc[mt][nt], afr[mt], bfr[nt][0], bfr[nt][1]);
        }
    }

    #pragma unroll
    for (int mt = 0; mt < 4; mt++) {
        #pragma unroll
        for (int nt = 0; nt < 4; nt++) {
            int row = bm + wm * 64 + mt * 16 + grp;
            int col = bn + wn * 32 + nt * 8 + qid * 2;
            float2 v0 = make_float2(acc[mt][nt][0], acc[mt][nt][1]);
            float2 v1 = make_float2(acc[mt][nt][2], acc[mt][nt][3]);
            if (HAS_BIAS) {
                float2 bb = *(const float2*)&bias[col];
                v0.x += bb.x; v0.y += bb.y;
                v1.x += bb.x; v1.y += bb.y;
            }
            if (ROUND_OUT) {
                v0.x = to_tf32(v0.x); v0.y = to_tf32(v0.y);
                v1.x = to_tf32(v1.x); v1.y = to_tf32(v1.y);
            }
            *(float2*)&Cmat[(size_t)row * Nx + col]       = v0;
            *(float2*)&Cmat[(size_t)(row + 8) * Nx + col] = v1;
        }
    }
}

// ---------------------------------------------------------------------------
// MMA flash-attention (tf32, causal), 128-query tiles, 8 warps,
// K-tiles of 32, cp.async double-buffered K/V, 2 CTAs/SM (88 KB smem).
// Q [q][d] stride 68 (LDSM A), K [j][d] stride 68 (LDSM B),
// V [j][d] stride 68 (scalar LDS B), P per-warp [16][36] (LDSM A).
// ---------------------------------------------------------------------------
__global__ __launch_bounds__(256, 2)
void attn_mma_kernel(const float* __restrict__ qkv, float* __restrict__ y)
{
    constexpr int STR  = 68;   // Q/K/V row stride (64 + 4 pad)
    constexpr int PSTR = 36;   // P row stride (32 + 4 pad)
    constexpr int KT   = 32;   // K-tile rows
    extern __shared__ float sm[];
    float* Qs  = sm;                     // [128 q][68]
    float* Ksb = Qs  + 128 * STR;        // [2][32 j][68]
    float* Vsb = Ksb + 2 * KT * STR;     // [2][32 j][68]
    float* Ps  = Vsb + 2 * KT * STR;     // [8 warps][16 r][36]

    const int tid  = threadIdx.x;
    const int lane = tid & 31;
    const int w    = tid >> 5;
    const int grp  = lane >> 2;
    const int qid  = lane & 3;
    const int qt   = (int)gridDim.x - 1 - (int)blockIdx.x;  // longest first
    const int bh   = blockIdx.y;
    const int b    = bh >> 4;
    const int h    = bh & 15;
    const float scale = 0.125f;

    const int a_lrow = ((lane >> 3) & 1) * 8 + (lane & 7);   // A-pattern row
    const int a_lcol = (lane >> 4) * 4;                      // A-pattern col
    const int b_lrow = (lane >> 4) * 8 + (lane & 7);         // B-pattern row
    const int b_lcol = ((lane >> 3) & 1) * 4;                // B-pattern col

    const float* qbase = qkv + (size_t)(b * SEQ) * (3 * CH) + h * HD;
    const float* kbase = qbase + CH;
    const float* vbase = qbase + 2 * CH;

    float* Pw = Ps + w * 16 * PSTR;
    const uint32_t uQ  = (uint32_t)__cvta_generic_to_shared(Qs);
    const uint32_t uKs = (uint32_t)__cvta_generic_to_shared(Ksb);
    const uint32_t uVs = (uint32_t)__cvta_generic_to_shared(Vsb);
    const uint32_t uP  = (uint32_t)__cvta_generic_to_shared(Pw);

    // Load Q tile 128x64 (8 float4 per thread), scale (exact), [q][d]
    #pragma unroll
    for (int t = 0; t < 8; t++) {
        int f   = tid + t * 256;
        int row = f >> 4;
        int c4  = (f & 15) * 4;
        float4 v = *(const float4*)&qbase[(size_t)(qt * 128 + row) * (3 * CH) + c4];
        v.x *= scale; v.y *= scale; v.z *= scale; v.w *= scale;
        *(float4*)&Qs[row * STR + c4] = v;
    }

    // cp.async K/V tile issue: 32 rows x 64 floats each; 2 float4/thread/tensor
    const int ld_row = tid >> 4;            // 0..15, +16 for second half
    const int ld_c4  = (tid & 15) * 4;
    auto issueKV = [&](int kt, int buf) {
        const float* Kg = kbase + (size_t)(kt * KT + ld_row) * (3 * CH) + ld_c4;
        const float* Vg = vbase + (size_t)(kt * KT + ld_row) * (3 * CH) + ld_c4;
        uint32_t dK = uKs + (uint32_t)((buf * KT + ld_row) * STR + ld_c4) * 4;
        uint32_t dV = uVs + (uint32_t)((buf * KT + ld_row) * STR + ld_c4) * 4;
        cp_async16(dK,                    Kg);
        cp_async16(dK + 16 * STR * 4,     Kg + (size_t)16 * (3 * CH));
        cp_async16(dV,                    Vg);
        cp_async16(dV + 16 * STR * 4,     Vg + (size_t)16 * (3 * CH));
        cp_commit();
    };

    float o[8][4];
    #pragma unroll
    for (int nt = 0; nt < 8; nt++)
        #pragma unroll
        for (int c = 0; c < 4; c++) o[nt][c] = 0.f;
    float m0 = -1e30f, m1 = -1e30f, l0 = 0.f, l1 = 0.f;

    const int row0 = 16 * w + grp;
    const int gi0  = qt * 128 + row0;
    const int gi1  = gi0 + 8;

    const int last = 4 * qt + 3;            // tiles of 32 cover (qt+1)*128 cols
    issueKV(0, 0);

    for (int kt = 0; kt <= last; kt++) {
        cp_wait0();
        __syncthreads();                 // tile kt visible; prev compute done
        if (kt < last) issueKV(kt + 1, (kt + 1) & 1);

        const int buf = kt & 1;
        const uint32_t uKb = uKs + (uint32_t)(buf * KT * STR) * 4;
        const float*   Vb  = Vsb + buf * KT * STR;

        // ---- S = Q @ K^T : 16x32 per warp; 8 k8-steps x 2 K-row-pairs
        float sfr[4][4];
        #pragma unroll
        for (int nt = 0; nt < 4; nt++)
            #pragma unroll
            for (int c = 0; c < 4; c++) sfr[nt][c] = 0.f;

        #pragma unroll
        for (int s = 0; s < 8; s++) {
            const int k0 = s * 8;
            uint32_t qf[4];
            ldsm_x4(qf, uQ + (uint32_t)(((16 * w + a_lrow) * STR + k0 + a_lcol) * 4));
            #pragma unroll
            for (int p = 0; p < 2; p++) {
                uint32_t kf[4];
                ldsm_x4(kf, uKb + (uint32_t)(((p * 16 + b_lrow) * STR + k0 + b_lcol) * 4));
                mma_tf32(sfr[2 * p    ], qf, kf[0], kf[1]);
                mma_tf32(sfr[2 * p + 1], qf, kf[2], kf[3]);
            }
        }

        // ---- causal mask (tiles kt >= 4*qt may intersect diagonal)
        if (kt >= 4 * qt) {
            #pragma unroll
            for (int nt = 0; nt < 4; nt++) {
                int j0 = kt * KT + nt * 8 + qid * 2;
                if (j0     > gi0) sfr[nt][0] = -1e30f;
                if (j0 + 1 > gi0) sfr[nt][1] = -1e30f;
                if (j0     > gi1) sfr[nt][2] = -1e30f;
                if (j0 + 1 > gi1) sfr[nt][3] = -1e30f;
            }
        }

        // ---- online softmax
        float mx0 = -1e30f, mx1 = -1e30f;
        #pragma unroll
        for (int nt = 0; nt < 4; nt++) {
            mx0 = fmaxf(mx0, fmaxf(sfr[nt][0], sfr[nt][1]));
            mx1 = fmaxf(mx1, fmaxf(sfr[nt][2], sfr[nt][3]));
        }
        #pragma unroll
        for (int off = 1; off <= 2; off <<= 1) {
            mx0 = fmaxf(mx0, __shfl_xor_sync(0xffffffffu, mx0, off));
            mx1 = fmaxf(mx1, __shfl_xor_sync(0xffffffffu, mx1, off));
        }
        float mnew0 = fmaxf(m0, mx0), mnew1 = fmaxf(m1, mx1);
        float alpha0 = __expf(m0 - mnew0), alpha1 = __expf(m1 - mnew1);
        float sum0 = 0.f, sum1 = 0.f;
        #pragma unroll
        for (int nt = 0; nt < 4; nt++) {
            sfr[nt][0] = __expf(sfr[nt][0] - mnew0);
            sfr[nt][1] = __expf(sfr[nt][1] - mnew0);
            sfr[nt][2] = __expf(sfr[nt][2] - mnew1);
            sfr[nt][3] = __expf(sfr[nt][3] - mnew1);
            sum0 += sfr[nt][0] + sfr[nt][1];
            sum1 += sfr[nt][2] + sfr[nt][3];
        }
        #pragma unroll
        for (int off = 1; off <= 2; off <<= 1) {
            sum0 += __shfl_xor_sync(0xffffffffu, sum0, off);
            sum1 += __shfl_xor_sync(0xffffffffu, sum1, off);
        }
        l0 = l0 * alpha0 + sum0;  m0 = mnew0;
        l1 = l1 * alpha1 + sum1;  m1 = mnew1;

        // ---- write P (tf32) to per-warp smem; rescale O
        #pragma unroll
        for (int nt = 0; nt < 4; nt++) {
            int cc = nt * 8 + qid * 2;
            float2 p0 = make_float2(to_tf32(sfr[nt][0]), to_tf32(sfr[nt][1]));
            float2 p1 = make_float2(to_tf32(sfr[nt][2]), to_tf32(sfr[nt][3]));
            *(float2*)&Pw[(grp    ) * PSTR + cc] = p0;
            *(float2*)&Pw[(grp + 8) * PSTR + cc] = p1;
        }
        #pragma unroll
        for (int nt = 0; nt < 8; nt++) {
            o[nt][0] *= alpha0; o[nt][1] *= alpha0;
            o[nt][2] *= alpha1; o[nt][3] *= alpha1;
        }
        __syncwarp();

        // ---- O += P @ V : 4 k8-steps (j = 32)
        #pragma unroll
        for (int s = 0; s < 4; s++) {
            const int k0 = s * 8;
            uint32_t pf[4];
            ldsm_x4(pf, uP + (uint32_t)((a_lrow * PSTR + k0 + a_lcol) * 4));
            const float* v0r = Vb + (k0 + qid    ) * STR + grp;
            const float* v1r = Vb + (k0 + qid + 4) * STR + grp;
            #pragma unroll
            for (int nt = 0; nt < 8; nt++) {
                uint32_t bf0 = __float_as_uint(v0r[nt * 8]);
                uint32_t bf1 = __float_as_uint(v1r[nt * 8]);
                mma_tf32(o[nt], pf, bf0, bf1);
            }
        }
        __syncwarp();   // done reading Pw before next tile overwrites
    }

    // ---- normalize + write y (tf32-rounded, feeds tf32 GEMM2)
    float inv0 = 1.0f / l0, inv1 = 1.0f / l1;
    #pragma unroll
    for (int nt = 0; nt < 8; nt++) {
        int d = nt * 8 + qid * 2;
        float2 v0 = make_float2(to_tf32(o[nt][0] * inv0), to_tf32(o[nt][1] * inv0));
        float2 v1 = make_float2(to_tf32(o[nt][2] * inv1), to_tf32(o[nt][3] * inv1));
        *(float2*)&y[(size_t)(b * SEQ + gi0) * CH + h * HD + d] = v0;
        *(float2*)&y[(size_t)(b * SEQ + gi1) * CH + h * HD + d] = v1;
    }
}

// ---------------------------------------------------------------------------

static constexpr int GEMM_SMEM = (2 * 128 * 36 + 2 * 32 * 132) * 4;   // 70656 B
static constexpr int ATTN_SMEM = (128 * 68 + 2 * 32 * 68 * 2 + 8 * 16 * 36) * 4;  // 88064 B

extern "C" void kernel_launch(void* const* d_in, const int* in_sizes, int n_in,
                              void* d_out, int out_size)
{
    (void)in_sizes; (void)n_in; (void)out_size;
    const float* x     = (const float*)d_in[0];
    const float* w_qkv = (const float*)d_in[1];
    const float* w_out = (const float*)d_in[2];
    const float* b_out = (const float*)d_in[3];
    float* out = (float*)d_out;

    float *qkv, *y, *xc, *wq, *wo;
    cudaGetSymbolAddress((void**)&qkv, g_qkv);
    cudaGetSymbolAddress((void**)&y,   g_y);
    cudaGetSymbolAddress((void**)&xc,  g_x);
    cudaGetSymbolAddress((void**)&wq,  g_wq);
    cudaGetSymbolAddress((void**)&wo,  g_wo);

    cudaFuncSetAttribute(gemm_tf32_kernel<false, true>,
                         cudaFuncAttributeMaxDynamicSharedMemorySize, GEMM_SMEM);
    cudaFuncSetAttribute(gemm_tf32_kernel<true, false>,
                         cudaFuncAttributeMaxDynamicSharedMemorySize, GEMM_SMEM);
    cudaFuncSetAttribute(attn_mma_kernel,
                         cudaFuncAttributeMaxDynamicSharedMemorySize, ATTN_SMEM);

    // 0) pre-round operands to tf32 (rna), once
    cvt_tf32_kernel<<<(MROWS * CH / 4 + 255) / 256, 256>>>(
        (const float4*)x, (float4*)xc, MROWS * CH / 4);
    cvt_tf32_kernel<<<(CH * 3 * CH / 4 + 255) / 256, 256>>>(
        (const float4*)w_qkv, (float4*)wq, CH * 3 * CH / 4);
    cvt_tf32_kernel<<<(CH * CH / 4 + 255) / 256, 256>>>(
        (const float4*)w_out, (float4*)wo, CH * CH / 4);

    // 1) qkv = x @ w_qkv  (tf32 TC, cp.async + ldmatrix), output tf32-rounded
    gemm_tf32_kernel<false, true><<<dim3(3 * CH / 128, MROWS / 128), 256, GEMM_SMEM>>>(
        xc, wq, nullptr, qkv, MROWS, 3 * CH, CH);

    // 2) causal flash attention -> y (tf32 TC, 128-q tiles, 32-row K-tiles,
    //    2 CTAs/SM), output tf32-rounded
    attn_mma_kernel<<<dim3(SEQ / 128, BATCH * NH), 256, ATTN_SMEM>>>(qkv, y);

    // 3) out = y @ w_out + b_out  (tf32 TC, cp.async + ldmatrix), fp32 output
    gemm_tf32_kernel<true, false><<<dim3(CH / 128, MROWS / 128), 256, GEMM_SMEM>>>(
        y, wo, b_out, out, MROWS, CH, CH);
}

// round 13
// speedup vs baseline: 3.0928x; 1.1328x over previous
#include <cuda_runtime.h>
#include <cstdint>

#define BATCH 2
#define SEQ   2048
#define CH    1024
#define NH    16
#define HD    64
#define MROWS (BATCH*SEQ)   /* 4096 */

// Scratch (allocation-free rule: __device__ globals)
__device__ float g_qkv[MROWS * 3 * CH];   // tf32-rounded qkv
__device__ float g_y  [MROWS * CH];       // tf32-rounded attn out
__device__ float g_x  [MROWS * CH];       // tf32-rounded x
__device__ float g_wqT[3 * CH * CH];      // transposed + tf32 w_qkv  [3C][C]
__device__ float g_woT[CH * CH];          // transposed + tf32 w_out  [C][C]

// ---------------------------------------------------------------------------
// TF32 / MMA / cp.async / ldmatrix helpers
// ---------------------------------------------------------------------------
__device__ __forceinline__ uint32_t to_tf32_bits(float x) {
    uint32_t y;
    asm("cvt.rna.tf32.f32 %0, %1;" : "=r"(y) : "f"(x));
    return y;
}
__device__ __forceinline__ float to_tf32(float x) {
    return __uint_as_float(to_tf32_bits(x));
}

__device__ __forceinline__ void mma_tf32(float c[4], const uint32_t a[4], const uint32_t b0, const uint32_t b1) {
    asm volatile(
        "mma.sync.aligned.m16n8k8.row.col.f32.tf32.tf32.f32 "
        "{%0,%1,%2,%3}, {%4,%5,%6,%7}, {%8,%9}, {%0,%1,%2,%3};"
        : "+f"(c[0]), "+f"(c[1]), "+f"(c[2]), "+f"(c[3])
        : "r"(a[0]), "r"(a[1]), "r"(a[2]), "r"(a[3]),
          "r"(b0), "r"(b1));
}

__device__ __forceinline__ void ldsm_x4(uint32_t r[4], uint32_t saddr) {
    asm volatile("ldmatrix.sync.aligned.m8n8.x4.shared.b16 {%0,%1,%2,%3}, [%4];"
        : "=r"(r[0]), "=r"(r[1]), "=r"(r[2]), "=r"(r[3]) : "r"(saddr));
}

__device__ __forceinline__ void cp_async16(uint32_t saddr, const void* gptr) {
    asm volatile("cp.async.cg.shared.global [%0], [%1], 16;" :: "r"(saddr), "l"(gptr));
}
__device__ __forceinline__ void cp_commit() { asm volatile("cp.async.commit_group;"); }
__device__ __forceinline__ void cp_wait0()  { asm volatile("cp.async.wait_group 0;"); }

// ---------------------------------------------------------------------------
// Elementwise tf32 rounding (float4 granularity)
// ---------------------------------------------------------------------------
__global__ void cvt_tf32_kernel(const float4* __restrict__ in, float4* __restrict__ out, int n4)
{
    int i = blockIdx.x * blockDim.x + threadIdx.x;
    if (i < n4) {
        float4 v = in[i];
        v.x = to_tf32(v.x); v.y = to_tf32(v.y);
        v.z = to_tf32(v.z); v.w = to_tf32(v.w);
        out[i] = v;
    }
}

// Transpose + tf32 round: in [R][Cc] -> out [Cc][R]
__global__ void transpose_tf32_kernel(const float* __restrict__ in, float* __restrict__ out,
                                      int R, int Cc)
{
    __shared__ float tile[32][33];
    int bx = blockIdx.x * 32;   // Cc base
    int by = blockIdx.y * 32;   // R base
    int tx = threadIdx.x, ty = threadIdx.y;
    #pragma unroll
    for (int i = 0; i < 32; i += 8)
        tile[ty + i][tx] = in[(size_t)(by + ty + i) * Cc + bx + tx];
    __syncthreads();
    #pragma unroll
    for (int i = 0; i < 32; i += 8)
        out[(size_t)(bx + ty + i) * R + by + tx] = to_tf32(tile[tx][ty + i]);
}

// ---------------------------------------------------------------------------
// TF32 tensor-core GEMM, cp.async double-buffered, BOTH operand fragments
// via ldmatrix. C = A(MxK) @ Bt^T (+bias); A [M][K], Bt [N][K] (pre-
// transposed weights). BM=128, BN=128, BK=32. 256 threads = 8 warps
// (2m x 4n), warp tile 64x32. A and B smem tiles are both [128][36].
// ---------------------------------------------------------------------------
template<bool HAS_BIAS, bool ROUND_OUT>
__global__ __launch_bounds__(256, 2)
void gemm_tf32_kernel(const float* __restrict__ A, const float* __restrict__ Bt,
                      const float* __restrict__ bias, float* __restrict__ Cmat,
                      int Mx, int Nx, int Kx)
{
    constexpr int BM = 128, BK = 32;
    constexpr int STR = 36;
    constexpr int TSZ = BM * STR;            // floats per tile buffer
    extern __shared__ float smem[];
    float* Asb[2] = { smem,           smem + TSZ };
    float* Bsb[2] = { smem + 2 * TSZ, smem + 3 * TSZ };

    const int tid  = threadIdx.x;
    const int lane = tid & 31;
    const int wid  = tid >> 5;
    const int wm   = wid >> 2;
    const int wn   = wid & 3;
    const int grp  = lane >> 2;
    const int qid  = lane & 3;
    const int bm = blockIdx.y * BM;
    const int bn = blockIdx.x * BM;

    const int a_lrow = ((lane >> 3) & 1) * 8 + (lane & 7);   // A-pattern row
    const int a_lcol = (lane >> 4) * 4;
    const int b_lrow = (lane >> 4) * 8 + (lane & 7);         // B-pattern row
    const int b_lcol = ((lane >> 3) & 1) * 4;

    const int g_row = tid >> 3, g_k4 = (tid & 7) * 4;        // cp.async coords

    const float* Aptr = A  + (size_t)(bm + g_row) * Kx + g_k4;
    const float* Bptr = Bt + (size_t)(bn + g_row) * Kx + g_k4;

    uint32_t sA[2], sB[2], uA[2], uB[2];
    #pragma unroll
    for (int b_ = 0; b_ < 2; b_++) {
        sA[b_] = (uint32_t)__cvta_generic_to_shared(Asb[b_] + g_row * STR + g_k4);
        sB[b_] = (uint32_t)__cvta_generic_to_shared(Bsb[b_] + g_row * STR + g_k4);
        uA[b_] = (uint32_t)__cvta_generic_to_shared(Asb[b_]);
        uB[b_] = (uint32_t)__cvta_generic_to_shared(Bsb[b_]);
    }

    const int ntiles = Kx / BK;

    auto issue = [&](int kt, int buf) {
        const float* Ag = Aptr + kt * BK;
        const float* Bg = Bptr + kt * BK;
        #pragma unroll
        for (int t = 0; t < 4; t++) {
            cp_async16(sA[buf] + t * (32 * STR * 4), Ag + (size_t)(t * 32) * Kx);
            cp_async16(sB[buf] + t * (32 * STR * 4), Bg + (size_t)(t * 32) * Kx);
        }
        cp_commit();
    };

    float acc[4][4][4];
    #pragma unroll
    for (int i = 0; i < 4; i++)
        #pragma unroll
        for (int j = 0; j < 4; j++)
            #pragma unroll
            for (int c = 0; c < 4; c++) acc[i][j][c] = 0.f;

    issue(0, 0);

    for (int kt = 0; kt < ntiles; kt++) {
        cp_wait0();
        __syncthreads();
        if (kt + 1 < ntiles) issue(kt + 1, (kt + 1) & 1);

        const int buf = kt & 1;
        const uint32_t uAb = uA[buf];
        const uint32_t uBb = uB[buf];
        #pragma unroll
        for (int s = 0; s < 4; s++) {
            const int k0 = s * 8;
            uint32_t afr[4][4];
            #pragma unroll
            for (int mt = 0; mt < 4; mt++)
                ldsm_x4(afr[mt], uAb + (uint32_t)(((wm * 64 + mt * 16 + a_lrow) * STR + k0 + a_lcol) * 4));
            #pragma unroll
            for (int p = 0; p < 2; p++) {
                uint32_t bfr[4];
                ldsm_x4(bfr, uBb + (uint32_t)(((wn * 32 + p * 16 + b_lrow) * STR + k0 + b_lcol) * 4));
                #pragma unroll
                for (int mt = 0; mt < 4; mt++) {
                    mma_tf32(acc[mt][2 * p    ], afr[mt], bfr[0], bfr[1]);
                    mma_tf32(acc[mt][2 * p + 1], afr[mt], bfr[2], bfr[3]);
                }
            }
        }
    }

    #pragma unroll
    for (int mt = 0; mt < 4; mt++) {
        #pragma unroll
        for (int nt = 0; nt < 4; nt++) {
            int row = bm + wm * 64 + mt * 16 + grp;
            int col = bn + wn * 32 + nt * 8 + qid * 2;
            float2 v0 = make_float2(acc[mt][nt][0], acc[mt][nt][1]);
            float2 v1 = make_float2(acc[mt][nt][2], acc[mt][nt][3]);
            if (HAS_BIAS) {
                float2 bb = *(const float2*)&bias[col];
                v0.x += bb.x; v0.y += bb.y;
                v1.x += bb.x; v1.y += bb.y;
            }
            if (ROUND_OUT) {
                v0.x = to_tf32(v0.x); v0.y = to_tf32(v0.y);
                v1.x = to_tf32(v1.x); v1.y = to_tf32(v1.y);
            }
            *(float2*)&Cmat[(size_t)row * Nx + col]       = v0;
            *(float2*)&Cmat[(size_t)(row + 8) * Nx + col] = v1;
        }
    }
}

// ---------------------------------------------------------------------------
// MMA flash-attention (tf32, causal), 128-query tiles, 8 warps,
// K-tiles of 32, cp.async double-buffered K/V, 2 CTAs/SM.
// Q-fragments hoisted into registers (loaded once, reused all K-tiles).
// ---------------------------------------------------------------------------
__global__ __launch_bounds__(256, 2)
void attn_mma_kernel(const float* __restrict__ qkv, float* __restrict__ y)
{
    constexpr int STR  = 68;   // Q/K/V row stride (64 + 4 pad)
    constexpr int PSTR = 36;   // P row stride (32 + 4 pad)
    constexpr int KT   = 32;   // K-tile rows
    extern __shared__ float sm[];
    float* Qs  = sm;                     // [128 q][68]
    float* Ksb = Qs  + 128 * STR;        // [2][32 j][68]
    float* Vsb = Ksb + 2 * KT * STR;     // [2][32 j][68]
    float* Ps  = Vsb + 2 * KT * STR;     // [8 warps][16 r][36]

    const int tid  = threadIdx.x;
    const int lane = tid & 31;
    const int w    = tid >> 5;
    const int grp  = lane >> 2;
    const int qid  = lane & 3;
    const int qt   = (int)gridDim.x - 1 - (int)blockIdx.x;  // longest first
    const int bh   = blockIdx.y;
    const int b    = bh >> 4;
    const int h    = bh & 15;
    const float scale = 0.125f;

    const int a_lrow = ((lane >> 3) & 1) * 8 + (lane & 7);
    const int a_lcol = (lane >> 4) * 4;
    const int b_lrow = (lane >> 4) * 8 + (lane & 7);
    const int b_lcol = ((lane >> 3) & 1) * 4;

    const float* qbase = qkv + (size_t)(b * SEQ) * (3 * CH) + h * HD;
    const float* kbase = qbase + CH;
    const float* vbase = qbase + 2 * CH;

    float* Pw = Ps + w * 16 * PSTR;
    const uint32_t uQ  = (uint32_t)__cvta_generic_to_shared(Qs);
    const uint32_t uKs = (uint32_t)__cvta_generic_to_shared(Ksb);
    const uint32_t uP  = (uint32_t)__cvta_generic_to_shared(Pw);

    // Load Q tile 128x64 into smem (scale exact), then hoist this warp's
    // A-fragments for all 8 k-steps into registers.
    #pragma unroll
    for (int t = 0; t < 8; t++) {
        int f   = tid + t * 256;
        int row = f >> 4;
        int c4  = (f & 15) * 4;
        float4 v = *(const float4*)&qbase[(size_t)(qt * 128 + row) * (3 * CH) + c4];
        v.x *= scale; v.y *= scale; v.z *= scale; v.w *= scale;
        *(float4*)&Qs[row * STR + c4] = v;
    }
    __syncthreads();
    uint32_t qfr[8][4];
    #pragma unroll
    for (int s = 0; s < 8; s++)
        ldsm_x4(qfr[s], uQ + (uint32_t)(((16 * w + a_lrow) * STR + s * 8 + a_lcol) * 4));

    // cp.async K/V tile issue: 32 rows x 64 floats each
    const int ld_row = tid >> 4;
    const int ld_c4  = (tid & 15) * 4;
    const uint32_t uVs = (uint32_t)__cvta_generic_to_shared(Vsb);
    auto issueKV = [&](int kt, int buf) {
        const float* Kg = kbase + (size_t)(kt * KT + ld_row) * (3 * CH) + ld_c4;
        const float* Vg = vbase + (size_t)(kt * KT + ld_row) * (3 * CH) + ld_c4;
        uint32_t dK = uKs + (uint32_t)((buf * KT + ld_row) * STR + ld_c4) * 4;
        uint32_t dV = uVs + (uint32_t)((buf * KT + ld_row) * STR + ld_c4) * 4;
        cp_async16(dK,                Kg);
        cp_async16(dK + 16 * STR * 4, Kg + (size_t)16 * (3 * CH));
        cp_async16(dV,                Vg);
        cp_async16(dV + 16 * STR * 4, Vg + (size_t)16 * (3 * CH));
        cp_commit();
    };

    float o[8][4];
    #pragma unroll
    for (int nt = 0; nt < 8; nt++)
        #pragma unroll
        for (int c = 0; c < 4; c++) o[nt][c] = 0.f;
    float m0 = -1e30f, m1 = -1e30f, l0 = 0.f, l1 = 0.f;

    const int row0 = 16 * w + grp;
    const int gi0  = qt * 128 + row0;
    const int gi1  = gi0 + 8;

    const int last = 4 * qt + 3;
    issueKV(0, 0);

    for (int kt = 0; kt <= last; kt++) {
        cp_wait0();
        __syncthreads();
        if (kt < last) issueKV(kt + 1, (kt + 1) & 1);

        const int buf = kt & 1;
        const uint32_t uKb = uKs + (uint32_t)(buf * KT * STR) * 4;
        const float*   Vb  = Vsb + buf * KT * STR;

        // ---- S = Q @ K^T : Q-frags from registers; 2 K-LDSM per k8 step
        float sfr[4][4];
        #pragma unroll
        for (int nt = 0; nt < 4; nt++)
            #pragma unroll
            for (int c = 0; c < 4; c++) sfr[nt][c] = 0.f;

        #pragma unroll
        for (int s = 0; s < 8; s++) {
            const int k0 = s * 8;
            #pragma unroll
            for (int p = 0; p < 2; p++) {
                uint32_t kf[4];
                ldsm_x4(kf, uKb + (uint32_t)(((p * 16 + b_lrow) * STR + k0 + b_lcol) * 4));
                mma_tf32(sfr[2 * p    ], qfr[s], kf[0], kf[1]);
                mma_tf32(sfr[2 * p + 1], qfr[s], kf[2], kf[3]);
            }
        }

        // ---- causal mask
        if (kt >= 4 * qt) {
            #pragma unroll
            for (int nt = 0; nt < 4; nt++) {
                int j0 = kt * KT + nt * 8 + qid * 2;
                if (j0     > gi0) sfr[nt][0] = -1e30f;
                if (j0 + 1 > gi0) sfr[nt][1] = -1e30f;
                if (j0     > gi1) sfr[nt][2] = -1e30f;
                if (j0 + 1 > gi1) sfr[nt][3] = -1e30f;
            }
        }

        // ---- online softmax
        float mx0 = -1e30f, mx1 = -1e30f;
        #pragma unroll
        for (int nt = 0; nt < 4; nt++) {
            mx0 = fmaxf(mx0, fmaxf(sfr[nt][0], sfr[nt][1]));
            mx1 = fmaxf(mx1, fmaxf(sfr[nt][2], sfr[nt][3]));
        }
        #pragma unroll
        for (int off = 1; off <= 2; off <<= 1) {
            mx0 = fmaxf(mx0, __shfl_xor_sync(0xffffffffu, mx0, off));
            mx1 = fmaxf(mx1, __shfl_xor_sync(0xffffffffu, mx1, off));
        }
        float mnew0 = fmaxf(m0, mx0), mnew1 = fmaxf(m1, mx1);
        float alpha0 = __expf(m0 - mnew0), alpha1 = __expf(m1 - mnew1);
        float sum0 = 0.f, sum1 = 0.f;
        #pragma unroll
        for (int nt = 0; nt < 4; nt++) {
            sfr[nt][0] = __expf(sfr[nt][0] - mnew0);
            sfr[nt][1] = __expf(sfr[nt][1] - mnew0);
            sfr[nt][2] = __expf(sfr[nt][2] - mnew1);
            sfr[nt][3] = __expf(sfr[nt][3] - mnew1);
            sum0 += sfr[nt][0] + sfr[nt][1];
            sum1 += sfr[nt][2] + sfr[nt][3];
        }
        #pragma unroll
        for (int off = 1; off <= 2; off <<= 1) {
            sum0 += __shfl_xor_sync(0xffffffffu, sum0, off);
            sum1 += __shfl_xor_sync(0xffffffffu, sum1, off);
        }
        l0 = l0 * alpha0 + sum0;  m0 = mnew0;
        l1 = l1 * alpha1 + sum1;  m1 = mnew1;

        // ---- write P (tf32) to per-warp smem; rescale O
        #pragma unroll
        for (int nt = 0; nt < 4; nt++) {
            int cc = nt * 8 + qid * 2;
            float2 p0 = make_float2(to_tf32(sfr[nt][0]), to_tf32(sfr[nt][1]));
            float2 p1 = make_float2(to_tf32(sfr[nt][2]), to_tf32(sfr[nt][3]));
            *(float2*)&Pw[(grp    ) * PSTR + cc] = p0;
            *(float2*)&Pw[(grp + 8) * PSTR + cc] = p1;
        }
        #pragma unroll
        for (int nt = 0; nt < 8; nt++) {
            o[nt][0] *= alpha0; o[nt][1] *= alpha0;
            o[nt][2] *= alpha1; o[nt][3] *= alpha1;
        }
        __syncwarp();

        // ---- O += P @ V : 4 k8-steps (j = 32)
        #pragma unroll
        for (int s = 0; s < 4; s++) {
            const int k0 = s * 8;
            uint32_t pf[4];
            ldsm_x4(pf, uP + (uint32_t)((a_lrow * PSTR + k0 + a_lcol) * 4));
            const float* v0r = Vb + (k0 + qid    ) * STR + grp;
            const float* v1r = Vb + (k0 + qid + 4) * STR + grp;
            #pragma unroll
            for (int nt = 0; nt < 8; nt++) {
                uint32_t bf0 = __float_as_uint(v0r[nt * 8]);
                uint32_t bf1 = __float_as_uint(v1r[nt * 8]);
                mma_tf32(o[nt], pf, bf0, bf1);
            }
        }
        __syncwarp();
    }

    // ---- normalize + write y (tf32-rounded, feeds tf32 GEMM2)
    float inv0 = 1.0f / l0, inv1 = 1.0f / l1;
    #pragma unroll
    for (int nt = 0; nt < 8; nt++) {
        int d = nt * 8 + qid * 2;
        float2 v0 = make_float2(to_tf32(o[nt][0] * inv0), to_tf32(o[nt][1] * inv0));
        float2 v1 = make_float2(to_tf32(o[nt][2] * inv1), to_tf32(o[nt][3] * inv1));
        *(float2*)&y[(size_t)(b * SEQ + gi0) * CH + h * HD + d] = v0;
        *(float2*)&y[(size_t)(b * SEQ + gi1) * CH + h * HD + d] = v1;
    }
}

// ---------------------------------------------------------------------------

static constexpr int GEMM_SMEM = (4 * 128 * 36) * 4;                              // 73728 B
static constexpr int ATTN_SMEM = (128 * 68 + 2 * 32 * 68 * 2 + 8 * 16 * 36) * 4;  // 88064 B

extern "C" void kernel_launch(void* const* d_in, const int* in_sizes, int n_in,
                              void* d_out, int out_size)
{
    (void)in_sizes; (void)n_in; (void)out_size;
    const float* x     = (const float*)d_in[0];
    const float* w_qkv = (const float*)d_in[1];
    const float* w_out = (const float*)d_in[2];
    const float* b_out = (const float*)d_in[3];
    float* out = (float*)d_out;

    float *qkv, *y, *xc, *wqT, *woT;
    cudaGetSymbolAddress((void**)&qkv, g_qkv);
    cudaGetSymbolAddress((void**)&y,   g_y);
    cudaGetSymbolAddress((void**)&xc,  g_x);
    cudaGetSymbolAddress((void**)&wqT, g_wqT);
    cudaGetSymbolAddress((void**)&woT, g_woT);

    cudaFuncSetAttribute(gemm_tf32_kernel<false, true>,
                         cudaFuncAttributeMaxDynamicSharedMemorySize, GEMM_SMEM);
    cudaFuncSetAttribute(gemm_tf32_kernel<true, false>,
                         cudaFuncAttributeMaxDynamicSharedMemorySize, GEMM_SMEM);
    cudaFuncSetAttribute(attn_mma_kernel,
                         cudaFuncAttributeMaxDynamicSharedMemorySize, ATTN_SMEM);

    // 0) operand prep: tf32-round x; transpose + tf32-round weights to [N][K]
    cvt_tf32_kernel<<<(MROWS * CH / 4 + 255) / 256, 256>>>(
        (const float4*)x, (float4*)xc, MROWS * CH / 4);
    transpose_tf32_kernel<<<dim3(3 * CH / 32, CH / 32), dim3(32, 8)>>>(
        w_qkv, wqT, CH, 3 * CH);
    transpose_tf32_kernel<<<dim3(CH / 32, CH / 32), dim3(32, 8)>>>(
        w_out, woT, CH, CH);

    // 1) qkv = x @ w_qkv  (tf32 TC, all-LDSM), output tf32-rounded
    gemm_tf32_kernel<false, true><<<dim3(3 * CH / 128, MROWS / 128), 256, GEMM_SMEM>>>(
        xc, wqT, nullptr, qkv, MROWS, 3 * CH, CH);

    // 2) causal flash attention -> y (tf32 TC, Q-frags in registers)
    attn_mma_kernel<<<dim3(SEQ / 128, BATCH * NH), 256, ATTN_SMEM>>>(qkv, y);

    // 3) out = y @ w_out + b_out  (tf32 TC, all-LDSM), fp32 output
    gemm_tf32_kernel<true, false><<<dim3(CH / 128, MROWS / 128), 256, GEMM_SMEM>>>(
        y, woT, b_out, out, MROWS, CH, CH);
}